// round 11
// baseline (speedup 1.0000x reference)
#include <cuda_runtime.h>
#include <cuda_bf16.h>
#include <cuda_fp16.h>
#include <cstdint>
#include <cstddef>

// ---------------------------------------------------------------------------
// HyperMoMixLinear on GB300 (sm_103a harness, PLAIN sm_103 ptx target).
// Big hypernet GEMMs (512x32768x1024, x2) on mma.sync fp16 at the measured
// legacy-HMMA ceiling (R9 structure: merged z=2 launch, 4-stage cp.async).
// R11 = R9 + ONE overlap: convert_w (DRAM-bound, no deps) forked onto a side
// stream, joined before bgemm. (R10 bundled 3 overlaps and regressed; the
// monarch||bgemm and biasor overlaps are reverted.)
// ---------------------------------------------------------------------------

#define T_TOK 512
#define C_DIM 256
#define IN_DIM 1024
#define OUT_DIM 1024
#define K_EXP 4
#define D_BIG 32768
#define KC 1024   // K_EXP * C_DIM  == GEMM K
#define W_ELEMS ((size_t)KC * D_BIG)

// -------------------- device scratch (no runtime allocation) ---------------
__device__ float g_c[T_TOK * C_DIM];
__device__ __half g_A16a[T_TOK * KC];
__device__ __half g_A16b[T_TOK * KC];
__device__ float g_coeffs[T_TOK * K_EXP];
__device__ float g_ratio[T_TOK];
__device__ float g_biasor[T_TOK * OUT_DIM];
__device__ float g_x1oT[T_TOK * OUT_DIM];          // stage-1 out, transposed
__device__ __half g_M[2 * (size_t)T_TOK * D_BIG];  // 2 x 32 MB (M1, M2)
__device__ __half g_W16[2 * W_ELEMS];              // 128 MB fp16 weights

__device__ __forceinline__ float silu_f(float v) {
    return v / (1.0f + __expf(-v));
}

__device__ __forceinline__ uint32_t smem_u32(const void* p) {
    uint32_t a;
    asm("{ .reg .u64 t; cvta.to.shared.u64 t, %1; cvt.u32.u64 %0, t; }"
        : "=r"(a) : "l"(p));
    return a;
}

#define CP_ASYNC16(dst, src) \
    asm volatile("cp.async.cg.shared.global [%0], [%1], 16;" \
                 :: "r"(dst), "l"(src) : "memory")
#define CP_COMMIT() asm volatile("cp.async.commit_group;" ::: "memory")
#define CP_WAIT2()  asm volatile("cp.async.wait_group 2;" ::: "memory")

#define LDSM4(r, addr) \
    asm volatile("ldmatrix.sync.aligned.m8n8.x4.shared.b16 {%0,%1,%2,%3}, [%4];" \
        : "=r"((r)[0]), "=r"((r)[1]), "=r"((r)[2]), "=r"((r)[3]) : "r"(addr))
#define LDSM4T(r, addr) \
    asm volatile("ldmatrix.sync.aligned.m8n8.x4.trans.shared.b16 {%0,%1,%2,%3}, [%4];" \
        : "=r"((r)[0]), "=r"((r)[1]), "=r"((r)[2]), "=r"((r)[3]) : "r"(addr))

#define MMA_F16(d, a, b0v, b1v) \
    asm volatile("mma.sync.aligned.m16n8k16.row.col.f32.f16.f16.f32 " \
        "{%0,%1,%2,%3}, {%4,%5,%6,%7}, {%8,%9}, {%0,%1,%2,%3};" \
        : "+f"((d)[0]), "+f"((d)[1]), "+f"((d)[2]), "+f"((d)[3]) \
        : "r"((a)[0]), "r"((a)[1]), "r"((a)[2]), "r"((a)[3]), \
          "r"(b0v), "r"(b1v))

// -------------------- W fp32 -> fp16 (both weights, one launch) ------------
__global__ void convert_w(const float* __restrict__ W1,
                          const float* __restrict__ W2,
                          __half* __restrict__ O)
{
    const float* W = blockIdx.y ? W2 : W1;
    __half* dst = O + (size_t)blockIdx.y * W_ELEMS;
    size_t base = ((size_t)blockIdx.x * 256 + threadIdx.x) * 8;
    float4 v0 = *(const float4*)(W + base);
    float4 v1 = *(const float4*)(W + base + 4);
    __half2 h0 = __floats2half2_rn(v0.x, v0.y);
    __half2 h1 = __floats2half2_rn(v0.z, v0.w);
    __half2 h2 = __floats2half2_rn(v1.x, v1.y);
    __half2 h3 = __floats2half2_rn(v1.z, v1.w);
    uint4 o;
    o.x = *(uint32_t*)&h0; o.y = *(uint32_t*)&h1;
    o.z = *(uint32_t*)&h2; o.w = *(uint32_t*)&h3;
    *(uint4*)(dst + base) = o;
}

// -------------------- small GEMM: 64x64x16 tiles, 4x4 per thread -----------
// EPI 0: out = acc + bias[n]          (fp32)
// EPI 1: out = silu(acc + bias[n])    (fp32)
// EPI 2: coeffs[m,kz]*silu(acc+bias)  -> fp16; z in [0,8): z>>2 picks stage
template<int EPI>
__global__ void sgemm64(const float* __restrict__ A, const float* __restrict__ B1,
                        float* __restrict__ Cmat,
                        int Kd, int lda, int ldb, int ldc,
                        const float* __restrict__ bias1,
                        const float* __restrict__ coeffs,
                        int b_zstride, int bias_zstride, int col_zstride,
                        __half* __restrict__ g16a,
                        const float* __restrict__ B2,
                        const float* __restrict__ bias2,
                        __half* __restrict__ g16b)
{
    const int BM = 64, BN = 64, BK = 16;
    __shared__ float As[BK][BM];
    __shared__ float Bs[BK][BN];
    int tid = threadIdx.x;
    int kz = blockIdx.z & 3;
    const float* B = B1;
    const float* bias = bias1;
    __half* g16 = g16a;
    if (EPI == 2 && blockIdx.z >= 4) { B = B2; bias = bias2; g16 = g16b; }
    B += (long)kz * b_zstride;
    bias += kz * bias_zstride;
    int m0 = blockIdx.y * BM;
    int n0 = blockIdx.x * BN;
    int tx = tid % 16, ty = tid / 16;
    int arow = tid / 4, aq = tid % 4;
    int brow = tid / 16, bq = tid % 16;
    float acc[4][4] = {};

    for (int k0 = 0; k0 < Kd; k0 += BK) {
        float4 av = *(const float4*)&A[(m0 + arow) * lda + k0 + aq * 4];
        As[aq * 4 + 0][arow] = av.x;
        As[aq * 4 + 1][arow] = av.y;
        As[aq * 4 + 2][arow] = av.z;
        As[aq * 4 + 3][arow] = av.w;
        *(float4*)&Bs[brow][bq * 4] =
            *(const float4*)&B[(k0 + brow) * ldb + n0 + bq * 4];
        __syncthreads();
#pragma unroll
        for (int k = 0; k < BK; k++) {
            float a[4], b[4];
#pragma unroll
            for (int i = 0; i < 4; i++) a[i] = As[k][ty * 4 + i];
#pragma unroll
            for (int j = 0; j < 4; j++) b[j] = Bs[k][tx * 4 + j];
#pragma unroll
            for (int i = 0; i < 4; i++)
#pragma unroll
                for (int j = 0; j < 4; j++) acc[i][j] += a[i] * b[j];
        }
        __syncthreads();
    }

#pragma unroll
    for (int i = 0; i < 4; i++) {
        int m = m0 + ty * 4 + i;
        float cf = 1.0f;
        if (EPI == 2) cf = coeffs[m * K_EXP + kz];
#pragma unroll
        for (int j = 0; j < 4; j++) {
            int n = n0 + tx * 4 + j;
            float v = acc[i][j] + bias[n];
            if (EPI == 1) v = silu_f(v);
            if (EPI == 2) {
                v = cf * silu_f(v);
                g16[m * ldc + kz * col_zstride + n] = __float2half(v);
            } else {
                Cmat[m * ldc + kz * col_zstride + n] = v;
            }
        }
    }
}

// -------------------- big GEMM on mma.sync (fp16, both operands cp.async) --
// z = blockIdx.z picks (A16, W16 plane, bB, Mout plane). Merged launch.
#define STG_SZ 32768
#define B_OFF 16384
#define NSTG 4
#define BGEMM_SMEM (NSTG * STG_SZ)   // 128 KB

__global__ void __launch_bounds__(256, 1) bgemm_half(
    const __half* __restrict__ A16a, const __half* __restrict__ A16b,
    const __half* __restrict__ W16,
    __half* __restrict__ Mbuf,
    const float* __restrict__ bB1, const float* __restrict__ bB2,
    const float* __restrict__ coeffs)
{
    extern __shared__ __align__(128) char smem[];
    const uint32_t sbase = smem_u32(smem);
    const int tid = threadIdx.x, wid = tid >> 5, lane = tid & 31;
    const int m0 = blockIdx.x * 128, n0 = blockIdx.y * 128;
    const int z = blockIdx.z;
    const int warp_m = wid & 1, warp_n = wid >> 1;

    const __half* A16 = z ? A16b : A16a;
    const __half* W = W16 + (size_t)z * W_ELEMS;
    const float* bB = z ? bB2 : bB1;
    __half* Mout = Mbuf + (size_t)z * T_TOK * D_BIG;

    float acc[4][4][4] = {};

    const int a_m = tid >> 2;
    const int a_q = tid & 3;
    const int b_k = tid >> 2;
    const int b_cq = tid & 3;

    const int aRow = warp_m * 64 + (lane & 15);
    const uint32_t axor = ((uint32_t)(aRow & 7)) << 4;
    const uint32_t aKhalf = ((lane >> 4) & 1) * 16;
    uint32_t kOff[4];
#pragma unroll
    for (int ks = 0; ks < 4; ks++)
        kOff[ks] = ((uint32_t)(ks * 32) + aKhalf) ^ axor;
    const uint32_t aBase = (uint32_t)aRow * 128;

    const int kLoc = (lane & 7) | (((lane >> 3) & 1) << 3);
    const uint32_t bxor = ((uint32_t)(kLoc & 7)) << 4;
    const uint32_t bBase = (uint32_t)kLoc * 256;
    uint32_t nbp[2];
#pragma unroll
    for (int p = 0; p < 2; p++)
        nbp[p] = ((uint32_t)((warp_n * 32 + p * 16 + ((lane >> 4) & 1) * 8) * 2)) ^ bxor;

    auto issue = [&](int it, int buf) {
        uint32_t s = sbase + buf * STG_SZ;
        int k0 = it * 64;
#pragma unroll
        for (int i = 0; i < 4; i++) {
            int m = a_m + (i & 1) * 64;
            int q = a_q + (i >> 1) * 4;
            const __half* src = A16 + (size_t)(m0 + m) * KC + k0 + q * 8;
            uint32_t dst = s + (uint32_t)m * 128 +
                           (((uint32_t)(q * 16)) ^ (((uint32_t)(m & 7)) << 4));
            CP_ASYNC16(dst, src);
        }
#pragma unroll
        for (int i = 0; i < 4; i++) {
            int chunk = b_cq + i * 4;
            const __half* src = W + (size_t)(k0 + b_k) * D_BIG + n0 + chunk * 8;
            uint32_t dst = s + B_OFF + (uint32_t)b_k * 256 +
                           (((uint32_t)(chunk * 16)) ^ (((uint32_t)(b_k & 7)) << 4));
            CP_ASYNC16(dst, src);
        }
        CP_COMMIT();
    };
    auto mmaStage = [&](int buf) {
        uint32_t sA = sbase + buf * STG_SZ;
        uint32_t sB = sA + B_OFF;
#pragma unroll
        for (int ks = 0; ks < 4; ks++) {
            uint32_t ah[4][4], bb[2][4];
#pragma unroll
            for (int mt = 0; mt < 4; mt++)
                LDSM4(ah[mt], sA + aBase + mt * 2048 + kOff[ks]);
#pragma unroll
            for (int p = 0; p < 2; p++)
                LDSM4T(bb[p], sB + ks * 4096 + bBase + nbp[p]);
#pragma unroll
            for (int mt = 0; mt < 4; mt++)
#pragma unroll
                for (int nt = 0; nt < 4; nt++)
                    MMA_F16(acc[mt][nt], ah[mt],
                            bb[nt >> 1][(nt & 1) * 2], bb[nt >> 1][(nt & 1) * 2 + 1]);
        }
    };

    issue(0, 0); issue(1, 1); issue(2, 2);

    for (int it = 0; it < 16; ++it) {
        CP_WAIT2();
        __syncthreads();
        if (it + 3 < 16) issue(it + 3, (it + 3) & (NSTG - 1));
        else CP_COMMIT();
        mmaStage(it & (NSTG - 1));
    }

    const int mw = m0 + warp_m * 64;
    const int nw = n0 + warp_n * 32;
    const int row = lane >> 2, colq = (lane & 3) * 2;
#pragma unroll
    for (int nt = 0; nt < 4; nt++) {
        int n = nw + nt * 8 + colq;
        float bv[K_EXP][2];
#pragma unroll
        for (int e = 0; e < K_EXP; e++) {
            bv[e][0] = bB[(size_t)e * D_BIG + n];
            bv[e][1] = bB[(size_t)e * D_BIG + n + 1];
        }
#pragma unroll
        for (int mt = 0; mt < 4; mt++) {
            int m = mw + mt * 16 + row;
            float4 c0 = *(const float4*)(coeffs + m * 4);
            float4 c1 = *(const float4*)(coeffs + (m + 8) * 4);
            float b00 = c0.x * bv[0][0] + c0.y * bv[1][0] + c0.z * bv[2][0] + c0.w * bv[3][0];
            float b01 = c0.x * bv[0][1] + c0.y * bv[1][1] + c0.z * bv[2][1] + c0.w * bv[3][1];
            float b10 = c1.x * bv[0][0] + c1.y * bv[1][0] + c1.z * bv[2][0] + c1.w * bv[3][0];
            float b11 = c1.x * bv[0][1] + c1.y * bv[1][1] + c1.z * bv[2][1] + c1.w * bv[3][1];
            __half2 h0 = __floats2half2_rn(acc[mt][nt][0] + b00, acc[mt][nt][1] + b01);
            __half2 h1 = __floats2half2_rn(acc[mt][nt][2] + b10, acc[mt][nt][3] + b11);
            *(__half2*)(Mout + (size_t)m * D_BIG + n) = h0;
            *(__half2*)(Mout + (size_t)(m + 8) * D_BIG + n) = h1;
        }
    }
}

// -------------------- mixer: coeffs + ratio per token ----------------------
__global__ void mixer_kernel(const float* __restrict__ c,
                             const float* __restrict__ Wm1, const float* __restrict__ bm1,
                             const float* __restrict__ Wm2, const float* __restrict__ bm2,
                             const float* __restrict__ Wr,  const float* __restrict__ br,
                             float* __restrict__ coeffs, float* __restrict__ ratio)
{
    __shared__ float cs[C_DIM];
    __shared__ float ms[C_DIM];
    __shared__ float red[C_DIM];
    __shared__ float lg[K_EXP];
    int t = blockIdx.x, tid = threadIdx.x;

    cs[tid] = c[t * C_DIM + tid];
    __syncthreads();

    float acc = bm1[tid];
#pragma unroll 8
    for (int i = 0; i < C_DIM; i++) acc += cs[i] * Wm1[i * C_DIM + tid];
    ms[tid] = silu_f(acc);
    red[tid] = cs[tid] * Wr[tid];
    __syncthreads();

    if (tid < K_EXP) {
        float l = bm2[tid];
#pragma unroll 8
        for (int i = 0; i < C_DIM; i++) l += ms[i] * Wm2[i * K_EXP + tid];
        lg[tid] = l;
    }
    for (int s = 128; s > 0; s >>= 1) {
        __syncthreads();
        if (tid < s) red[tid] += red[tid + s];
    }
    __syncthreads();

    if (tid == 0) {
        ratio[t] = red[0] + br[0];
        float mx = fmaxf(fmaxf(lg[0], lg[1]), fmaxf(lg[2], lg[3]));
        float e0 = __expf(lg[0] - mx), e1 = __expf(lg[1] - mx);
        float e2 = __expf(lg[2] - mx), e3 = __expf(lg[3] - mx);
        float inv = 1.0f / (e0 + e1 + e2 + e3);
        coeffs[t * 4 + 0] = e0 * inv;
        coeffs[t * 4 + 1] = e1 * inv;
        coeffs[t * 4 + 2] = e2 * inv;
        coeffs[t * 4 + 3] = e3 * inv;
    }
}

// -------------------- Monarch stage: per-(token,g) 32x32 GEMV (fp16 M) -----
template<int STAGE>
__global__ void monarch_kernel(const float* __restrict__ X,
                               const __half* __restrict__ Mbuf,
                               float* __restrict__ out,
                               const float* __restrict__ ratio,
                               const float* __restrict__ biasor)
{
    __shared__ float xs[1024];
    int t = blockIdx.x;
    int tid = threadIdx.x;   // 256
#pragma unroll
    for (int i = tid; i < 1024; i += 256) xs[i] = X[t * 1024 + i];
    __syncthreads();

    int o = tid & 31, w = tid >> 5;
    const __half* Mrow = Mbuf + (size_t)t * D_BIG;
#pragma unroll
    for (int gi = 0; gi < 4; gi++) {
        int g = w * 4 + gi;
        float acc = 0.0f;
        const __half* mp = Mrow + g * 1024 + o;
#pragma unroll
        for (int i = 0; i < 32; i++) acc += xs[g * 32 + i] * __half2float(mp[i * 32]);
        if (STAGE == 1) {
            out[t * 1024 + o * 32 + g] = acc;           // transposed for stage 2
        } else {
            int idx = t * 1024 + g * 32 + o;
            out[idx] = acc * ratio[t] + biasor[idx];
        }
    }
}

// ---------------------------------------------------------------------------
extern "C" void kernel_launch(void* const* d_in, const int* in_sizes, int n_in,
                              void* d_out, int out_size)
{
    const float* x   = (const float*)d_in[0];
    const float* Wc  = (const float*)d_in[1];
    const float* bc  = (const float*)d_in[2];
    const float* W1a = (const float*)d_in[3];
    const float* b1a = (const float*)d_in[4];
    const float* W1b = (const float*)d_in[5];
    const float* b1b = (const float*)d_in[6];
    const float* W2a = (const float*)d_in[7];
    const float* b2a = (const float*)d_in[8];
    const float* W2b = (const float*)d_in[9];
    const float* b2b = (const float*)d_in[10];
    const float* Wm1 = (const float*)d_in[11];
    const float* bm1 = (const float*)d_in[12];
    const float* Wm2 = (const float*)d_in[13];
    const float* bm2 = (const float*)d_in[14];
    const float* Wb  = (const float*)d_in[15];
    const float* bb  = (const float*)d_in[16];
    const float* Wr  = (const float*)d_in[17];
    const float* br  = (const float*)d_in[18];
    float* out = (float*)d_out;

    float *p_c, *p_co, *p_ra, *p_bi, *p_x1;
    __half *p_a, *p_b, *p_M, *p_w16;
    cudaGetSymbolAddress((void**)&p_c,   g_c);
    cudaGetSymbolAddress((void**)&p_a,   g_A16a);
    cudaGetSymbolAddress((void**)&p_b,   g_A16b);
    cudaGetSymbolAddress((void**)&p_co,  g_coeffs);
    cudaGetSymbolAddress((void**)&p_ra,  g_ratio);
    cudaGetSymbolAddress((void**)&p_bi,  g_biasor);
    cudaGetSymbolAddress((void**)&p_x1,  g_x1oT);
    cudaGetSymbolAddress((void**)&p_M,   g_M);
    cudaGetSymbolAddress((void**)&p_w16, g_W16);

    static cudaStream_t sW = nullptr;
    static cudaEvent_t evRoot, evW;
    if (!sW) {
        cudaStreamCreateWithFlags(&sW, cudaStreamNonBlocking);
        cudaEventCreateWithFlags(&evRoot, cudaEventDisableTiming);
        cudaEventCreateWithFlags(&evW,    cudaEventDisableTiming);
        cudaFuncSetAttribute(bgemm_half,
                             cudaFuncAttributeMaxDynamicSharedMemorySize,
                             BGEMM_SMEM);
    }

    // ---- fork: convert_w on side stream, joined before bgemm ----
    cudaEventRecord(evRoot, 0);
    cudaStreamWaitEvent(sW, evRoot, 0);
    convert_w<<<dim3(16384, 2), 256, 0, sW>>>(W1b, W2b, p_w16);
    cudaEventRecord(evW, sW);

    // main: c = silu(x @ Wc + bc)
    sgemm64<1><<<dim3(C_DIM / 64, T_TOK / 64, 1), 256>>>(
        x, Wc, p_c, IN_DIM, IN_DIM, C_DIM, C_DIM, bc, nullptr, 0, 0, 0,
        nullptr, nullptr, nullptr, nullptr);

    // main: coeffs (softmax), ratio
    mixer_kernel<<<T_TOK, C_DIM>>>(p_c, Wm1, bm1, Wm2, bm2, Wr, br, p_co, p_ra);

    // main: biasor = c @ Wb + bb
    sgemm64<0><<<dim3(OUT_DIM / 64, T_TOK / 64, 1), 256>>>(
        p_c, Wb, p_bi, C_DIM, C_DIM, OUT_DIM, OUT_DIM, bb, nullptr, 0, 0, 0,
        nullptr, nullptr, nullptr, nullptr);

    // main: BOTH expert-gens in one launch -> fp16 A operands
    sgemm64<2><<<dim3(C_DIM / 64, T_TOK / 64, 2 * K_EXP), 256>>>(
        p_c, W1a, nullptr, C_DIM, C_DIM, C_DIM, KC, b1a, p_co,
        C_DIM * C_DIM, C_DIM, C_DIM, p_a, W2a, b2a, p_b);

    // join convert_w, then merged bgemm (z picks stage)
    cudaStreamWaitEvent(0, evW, 0);
    bgemm_half<<<dim3(T_TOK / 128, D_BIG / 128, 2), 256, BGEMM_SMEM>>>(
        p_a, p_b, p_w16, p_M, b1b, b2b, p_co);

    // monarch stage 1 (writes transposed)
    monarch_kernel<1><<<T_TOK, 256>>>(x, p_M, p_x1, nullptr, nullptr);

    // monarch stage 2 + final epilogue
    monarch_kernel<2><<<T_TOK, 256>>>(
        p_x1, p_M + (size_t)T_TOK * D_BIG, out, p_ra, p_bi);
}

// round 12
// speedup vs baseline: 1.3546x; 1.3546x over previous
#include <cuda_runtime.h>
#include <cuda_bf16.h>
#include <cuda_fp16.h>
#include <cstdint>
#include <cstddef>

// ---------------------------------------------------------------------------
// HyperMoMixLinear on GB300 (sm_103a harness, PLAIN sm_103 ptx target).
// Big hypernet GEMMs (512x32768x1024, x2) on mma.sync fp16, 1-term.
// R12: single stream (R10/R11 proved graph forks cost ~100us here).
//   - bgemm: NSTG=2 (64KB smem) -> 2 CTAs/SM, R6's one-sync issue-ahead loop.
//   - biasor merged into the expert-gen launch as z=8.
// ---------------------------------------------------------------------------

#define T_TOK 512
#define C_DIM 256
#define IN_DIM 1024
#define OUT_DIM 1024
#define K_EXP 4
#define D_BIG 32768
#define KC 1024   // K_EXP * C_DIM  == GEMM K
#define W_ELEMS ((size_t)KC * D_BIG)

// -------------------- device scratch (no runtime allocation) ---------------
__device__ float g_c[T_TOK * C_DIM];
__device__ __half g_A16a[T_TOK * KC];
__device__ __half g_A16b[T_TOK * KC];
__device__ float g_coeffs[T_TOK * K_EXP];
__device__ float g_ratio[T_TOK];
__device__ float g_biasor[T_TOK * OUT_DIM];
__device__ float g_x1oT[T_TOK * OUT_DIM];          // stage-1 out, transposed
__device__ __half g_M[2 * (size_t)T_TOK * D_BIG];  // 2 x 32 MB (M1, M2)
__device__ __half g_W16[2 * W_ELEMS];              // 128 MB fp16 weights

__device__ __forceinline__ float silu_f(float v) {
    return v / (1.0f + __expf(-v));
}

__device__ __forceinline__ uint32_t smem_u32(const void* p) {
    uint32_t a;
    asm("{ .reg .u64 t; cvta.to.shared.u64 t, %1; cvt.u32.u64 %0, t; }"
        : "=r"(a) : "l"(p));
    return a;
}

#define CP_ASYNC16(dst, src) \
    asm volatile("cp.async.cg.shared.global [%0], [%1], 16;" \
                 :: "r"(dst), "l"(src) : "memory")
#define CP_COMMIT() asm volatile("cp.async.commit_group;" ::: "memory")
#define CP_WAIT0()  asm volatile("cp.async.wait_group 0;" ::: "memory")

#define LDSM4(r, addr) \
    asm volatile("ldmatrix.sync.aligned.m8n8.x4.shared.b16 {%0,%1,%2,%3}, [%4];" \
        : "=r"((r)[0]), "=r"((r)[1]), "=r"((r)[2]), "=r"((r)[3]) : "r"(addr))
#define LDSM4T(r, addr) \
    asm volatile("ldmatrix.sync.aligned.m8n8.x4.trans.shared.b16 {%0,%1,%2,%3}, [%4];" \
        : "=r"((r)[0]), "=r"((r)[1]), "=r"((r)[2]), "=r"((r)[3]) : "r"(addr))

#define MMA_F16(d, a, b0v, b1v) \
    asm volatile("mma.sync.aligned.m16n8k16.row.col.f32.f16.f16.f32 " \
        "{%0,%1,%2,%3}, {%4,%5,%6,%7}, {%8,%9}, {%0,%1,%2,%3};" \
        : "+f"((d)[0]), "+f"((d)[1]), "+f"((d)[2]), "+f"((d)[3]) \
        : "r"((a)[0]), "r"((a)[1]), "r"((a)[2]), "r"((a)[3]), \
          "r"(b0v), "r"(b1v))

// -------------------- W fp32 -> fp16 (both weights, one launch) ------------
__global__ void convert_w(const float* __restrict__ W1,
                          const float* __restrict__ W2,
                          __half* __restrict__ O)
{
    const float* W = blockIdx.y ? W2 : W1;
    __half* dst = O + (size_t)blockIdx.y * W_ELEMS;
    size_t base = ((size_t)blockIdx.x * 256 + threadIdx.x) * 8;
    float4 v0 = *(const float4*)(W + base);
    float4 v1 = *(const float4*)(W + base + 4);
    __half2 h0 = __floats2half2_rn(v0.x, v0.y);
    __half2 h1 = __floats2half2_rn(v0.z, v0.w);
    __half2 h2 = __floats2half2_rn(v1.x, v1.y);
    __half2 h3 = __floats2half2_rn(v1.z, v1.w);
    uint4 o;
    o.x = *(uint32_t*)&h0; o.y = *(uint32_t*)&h1;
    o.z = *(uint32_t*)&h2; o.w = *(uint32_t*)&h3;
    *(uint4*)(dst + base) = o;
}

// -------------------- compressor GEMM: c = silu(x @ Wc + bc) ---------------
__global__ void sgemm_c(const float* __restrict__ A, const float* __restrict__ B,
                        float* __restrict__ Cmat, const float* __restrict__ bias)
{
    const int BM = 64, BN = 64, BK = 16;
    __shared__ float As[BK][BM];
    __shared__ float Bs[BK][BN];
    int tid = threadIdx.x;
    int m0 = blockIdx.y * BM;
    int n0 = blockIdx.x * BN;
    int tx = tid % 16, ty = tid / 16;
    int arow = tid / 4, aq = tid % 4;
    int brow = tid / 16, bq = tid % 16;
    float acc[4][4] = {};

    for (int k0 = 0; k0 < IN_DIM; k0 += BK) {
        float4 av = *(const float4*)&A[(m0 + arow) * IN_DIM + k0 + aq * 4];
        As[aq * 4 + 0][arow] = av.x;
        As[aq * 4 + 1][arow] = av.y;
        As[aq * 4 + 2][arow] = av.z;
        As[aq * 4 + 3][arow] = av.w;
        *(float4*)&Bs[brow][bq * 4] =
            *(const float4*)&B[(k0 + brow) * C_DIM + n0 + bq * 4];
        __syncthreads();
#pragma unroll
        for (int k = 0; k < BK; k++) {
            float a[4], b[4];
#pragma unroll
            for (int i = 0; i < 4; i++) a[i] = As[k][ty * 4 + i];
#pragma unroll
            for (int j = 0; j < 4; j++) b[j] = Bs[k][tx * 4 + j];
#pragma unroll
            for (int i = 0; i < 4; i++)
#pragma unroll
                for (int j = 0; j < 4; j++) acc[i][j] += a[i] * b[j];
        }
        __syncthreads();
    }

#pragma unroll
    for (int i = 0; i < 4; i++) {
        int m = m0 + ty * 4 + i;
#pragma unroll
        for (int j = 0; j < 4; j++) {
            int n = n0 + tx * 4 + j;
            Cmat[m * C_DIM + n] = silu_f(acc[i][j] + bias[n]);
        }
    }
}

// -------------------- merged generator + biasor kernel ---------------------
// grid (16, 8, 9):
//   z in [0,8): expert-gen (kz = z&3, stage = z>>2): uses x<4 only.
//       g16[m, kz*256+n] = coeffs[m,kz] * silu(c @ Wsa[kz] + bsa[kz])  (fp16)
//   z == 8: biasor[m, n] = c @ Wb + bb  over full N=1024 (all 16 x-blocks)
__global__ void gen_all(const float* __restrict__ c,
                        const float* __restrict__ W1a, const float* __restrict__ b1a,
                        const float* __restrict__ W2a, const float* __restrict__ b2a,
                        const float* __restrict__ Wb,  const float* __restrict__ bb,
                        const float* __restrict__ coeffs,
                        __half* __restrict__ g16a, __half* __restrict__ g16b,
                        float* __restrict__ biasor)
{
    const int BM = 64, BN = 64, BK = 16;
    int z = blockIdx.z;
    bool isB = (z == 8);
    if (!isB && blockIdx.x >= 4) return;

    const float* B;
    const float* bias;
    __half* g16 = nullptr;
    int ldb, kz = z & 3;
    if (isB) { B = Wb; bias = bb; ldb = OUT_DIM; }
    else {
        B = (z < 4 ? W1a : W2a) + (long)kz * C_DIM * C_DIM;
        bias = (z < 4 ? b1a : b2a) + kz * C_DIM;
        g16 = (z < 4 ? g16a : g16b);
        ldb = C_DIM;
    }

    __shared__ float As[BK][BM];
    __shared__ float Bs[BK][BN];
    int tid = threadIdx.x;
    int m0 = blockIdx.y * BM;
    int n0 = blockIdx.x * BN;
    int tx = tid % 16, ty = tid / 16;
    int arow = tid / 4, aq = tid % 4;
    int brow = tid / 16, bq = tid % 16;
    float acc[4][4] = {};

    for (int k0 = 0; k0 < C_DIM; k0 += BK) {
        float4 av = *(const float4*)&c[(m0 + arow) * C_DIM + k0 + aq * 4];
        As[aq * 4 + 0][arow] = av.x;
        As[aq * 4 + 1][arow] = av.y;
        As[aq * 4 + 2][arow] = av.z;
        As[aq * 4 + 3][arow] = av.w;
        *(float4*)&Bs[brow][bq * 4] =
            *(const float4*)&B[(k0 + brow) * ldb + n0 + bq * 4];
        __syncthreads();
#pragma unroll
        for (int k = 0; k < BK; k++) {
            float a[4], b[4];
#pragma unroll
            for (int i = 0; i < 4; i++) a[i] = As[k][ty * 4 + i];
#pragma unroll
            for (int j = 0; j < 4; j++) b[j] = Bs[k][tx * 4 + j];
#pragma unroll
            for (int i = 0; i < 4; i++)
#pragma unroll
                for (int j = 0; j < 4; j++) acc[i][j] += a[i] * b[j];
        }
        __syncthreads();
    }

#pragma unroll
    for (int i = 0; i < 4; i++) {
        int m = m0 + ty * 4 + i;
        float cf = isB ? 1.0f : coeffs[m * K_EXP + kz];
#pragma unroll
        for (int j = 0; j < 4; j++) {
            int n = n0 + tx * 4 + j;
            float v = acc[i][j] + bias[n];
            if (isB) {
                biasor[m * OUT_DIM + n] = v;
            } else {
                v = cf * silu_f(v);
                g16[m * KC + kz * C_DIM + n] = __float2half(v);
            }
        }
    }
}

// -------------------- big GEMM on mma.sync (fp16, both operands cp.async) --
// z = blockIdx.z picks (A16, W16 plane, bB, Mout plane). Merged launch.
// NSTG=2 (64 KB smem) -> 2 CTAs/SM; R6-style one-sync issue-ahead loop.
#define STG_SZ 32768
#define B_OFF 16384
#define NSTG 2
#define BGEMM_SMEM (NSTG * STG_SZ)   // 64 KB

__global__ void __launch_bounds__(256, 2) bgemm_half(
    const __half* __restrict__ A16a, const __half* __restrict__ A16b,
    const __half* __restrict__ W16,
    __half* __restrict__ Mbuf,
    const float* __restrict__ bB1, const float* __restrict__ bB2,
    const float* __restrict__ coeffs)
{
    extern __shared__ __align__(128) char smem[];
    const uint32_t sbase = smem_u32(smem);
    const int tid = threadIdx.x, wid = tid >> 5, lane = tid & 31;
    const int m0 = blockIdx.x * 128, n0 = blockIdx.y * 128;
    const int z = blockIdx.z;
    const int warp_m = wid & 1, warp_n = wid >> 1;

    const __half* A16 = z ? A16b : A16a;
    const __half* W = W16 + (size_t)z * W_ELEMS;
    const float* bB = z ? bB2 : bB1;
    __half* Mout = Mbuf + (size_t)z * T_TOK * D_BIG;

    float acc[4][4][4] = {};

    const int a_m = tid >> 2;
    const int a_q = tid & 3;
    const int b_k = tid >> 2;
    const int b_cq = tid & 3;

    const int aRow = warp_m * 64 + (lane & 15);
    const uint32_t axor = ((uint32_t)(aRow & 7)) << 4;
    const uint32_t aKhalf = ((lane >> 4) & 1) * 16;
    uint32_t kOff[4];
#pragma unroll
    for (int ks = 0; ks < 4; ks++)
        kOff[ks] = ((uint32_t)(ks * 32) + aKhalf) ^ axor;
    const uint32_t aBase = (uint32_t)aRow * 128;

    const int kLoc = (lane & 7) | (((lane >> 3) & 1) << 3);
    const uint32_t bxor = ((uint32_t)(kLoc & 7)) << 4;
    const uint32_t bBase = (uint32_t)kLoc * 256;
    uint32_t nbp[2];
#pragma unroll
    for (int p = 0; p < 2; p++)
        nbp[p] = ((uint32_t)((warp_n * 32 + p * 16 + ((lane >> 4) & 1) * 8) * 2)) ^ bxor;

    auto issue = [&](int it, int buf) {
        uint32_t s = sbase + buf * STG_SZ;
        int k0 = it * 64;
#pragma unroll
        for (int i = 0; i < 4; i++) {
            int m = a_m + (i & 1) * 64;
            int q = a_q + (i >> 1) * 4;
            const __half* src = A16 + (size_t)(m0 + m) * KC + k0 + q * 8;
            uint32_t dst = s + (uint32_t)m * 128 +
                           (((uint32_t)(q * 16)) ^ (((uint32_t)(m & 7)) << 4));
            CP_ASYNC16(dst, src);
        }
#pragma unroll
        for (int i = 0; i < 4; i++) {
            int chunk = b_cq + i * 4;
            const __half* src = W + (size_t)(k0 + b_k) * D_BIG + n0 + chunk * 8;
            uint32_t dst = s + B_OFF + (uint32_t)b_k * 256 +
                           (((uint32_t)(chunk * 16)) ^ (((uint32_t)(b_k & 7)) << 4));
            CP_ASYNC16(dst, src);
        }
        CP_COMMIT();
    };
    auto mmaStage = [&](int buf) {
        uint32_t sA = sbase + buf * STG_SZ;
        uint32_t sB = sA + B_OFF;
#pragma unroll
        for (int ks = 0; ks < 4; ks++) {
            uint32_t ah[4][4], bb[2][4];
#pragma unroll
            for (int mt = 0; mt < 4; mt++)
                LDSM4(ah[mt], sA + aBase + mt * 2048 + kOff[ks]);
#pragma unroll
            for (int p = 0; p < 2; p++)
                LDSM4T(bb[p], sB + ks * 4096 + bBase + nbp[p]);
#pragma unroll
            for (int mt = 0; mt < 4; mt++)
#pragma unroll
                for (int nt = 0; nt < 4; nt++)
                    MMA_F16(acc[mt][nt], ah[mt],
                            bb[nt >> 1][(nt & 1) * 2], bb[nt >> 1][(nt & 1) * 2 + 1]);
        }
    };

    // prologue: fill stage 0, wait, sync
    issue(0, 0);
    CP_WAIT0();
    __syncthreads();

    // main loop: issue-ahead double buffer, ONE sync per iter (R6 skeleton):
    // the end-of-iter CP_WAIT0+sync covers both "next data ready" and
    // "current buffer fully consumed before overwrite next iter".
    for (int it = 0; it < 16; ++it) {
        int cur = it & 1, nxt = cur ^ 1;
        if (it < 15) issue(it + 1, nxt);
        mmaStage(cur);
        CP_WAIT0();
        __syncthreads();
    }

    // epilogue: mixed-expert bias, fp16 stores
    const int mw = m0 + warp_m * 64;
    const int nw = n0 + warp_n * 32;
    const int row = lane >> 2, colq = (lane & 3) * 2;
#pragma unroll
    for (int nt = 0; nt < 4; nt++) {
        int n = nw + nt * 8 + colq;
        float bv[K_EXP][2];
#pragma unroll
        for (int e = 0; e < K_EXP; e++) {
            bv[e][0] = bB[(size_t)e * D_BIG + n];
            bv[e][1] = bB[(size_t)e * D_BIG + n + 1];
        }
#pragma unroll
        for (int mt = 0; mt < 4; mt++) {
            int m = mw + mt * 16 + row;
            float4 c0 = *(const float4*)(coeffs + m * 4);
            float4 c1 = *(const float4*)(coeffs + (m + 8) * 4);
            float b00 = c0.x * bv[0][0] + c0.y * bv[1][0] + c0.z * bv[2][0] + c0.w * bv[3][0];
            float b01 = c0.x * bv[0][1] + c0.y * bv[1][1] + c0.z * bv[2][1] + c0.w * bv[3][1];
            float b10 = c1.x * bv[0][0] + c1.y * bv[1][0] + c1.z * bv[2][0] + c1.w * bv[3][0];
            float b11 = c1.x * bv[0][1] + c1.y * bv[1][1] + c1.z * bv[2][1] + c1.w * bv[3][1];
            __half2 h0 = __floats2half2_rn(acc[mt][nt][0] + b00, acc[mt][nt][1] + b01);
            __half2 h1 = __floats2half2_rn(acc[mt][nt][2] + b10, acc[mt][nt][3] + b11);
            *(__half2*)(Mout + (size_t)m * D_BIG + n) = h0;
            *(__half2*)(Mout + (size_t)(m + 8) * D_BIG + n) = h1;
        }
    }
}

// -------------------- mixer: coeffs + ratio per token ----------------------
__global__ void mixer_kernel(const float* __restrict__ c,
                             const float* __restrict__ Wm1, const float* __restrict__ bm1,
                             const float* __restrict__ Wm2, const float* __restrict__ bm2,
                             const float* __restrict__ Wr,  const float* __restrict__ br,
                             float* __restrict__ coeffs, float* __restrict__ ratio)
{
    __shared__ float cs[C_DIM];
    __shared__ float ms[C_DIM];
    __shared__ float red[C_DIM];
    __shared__ float lg[K_EXP];
    int t = blockIdx.x, tid = threadIdx.x;

    cs[tid] = c[t * C_DIM + tid];
    __syncthreads();

    float acc = bm1[tid];
#pragma unroll 8
    for (int i = 0; i < C_DIM; i++) acc += cs[i] * Wm1[i * C_DIM + tid];
    ms[tid] = silu_f(acc);
    red[tid] = cs[tid] * Wr[tid];
    __syncthreads();

    if (tid < K_EXP) {
        float l = bm2[tid];
#pragma unroll 8
        for (int i = 0; i < C_DIM; i++) l += ms[i] * Wm2[i * K_EXP + tid];
        lg[tid] = l;
    }
    for (int s = 128; s > 0; s >>= 1) {
        __syncthreads();
        if (tid < s) red[tid] += red[tid + s];
    }
    __syncthreads();

    if (tid == 0) {
        ratio[t] = red[0] + br[0];
        float mx = fmaxf(fmaxf(lg[0], lg[1]), fmaxf(lg[2], lg[3]));
        float e0 = __expf(lg[0] - mx), e1 = __expf(lg[1] - mx);
        float e2 = __expf(lg[2] - mx), e3 = __expf(lg[3] - mx);
        float inv = 1.0f / (e0 + e1 + e2 + e3);
        coeffs[t * 4 + 0] = e0 * inv;
        coeffs[t * 4 + 1] = e1 * inv;
        coeffs[t * 4 + 2] = e2 * inv;
        coeffs[t * 4 + 3] = e3 * inv;
    }
}

// -------------------- Monarch stage: per-(token,g) 32x32 GEMV (fp16 M) -----
template<int STAGE>
__global__ void monarch_kernel(const float* __restrict__ X,
                               const __half* __restrict__ Mbuf,
                               float* __restrict__ out,
                               const float* __restrict__ ratio,
                               const float* __restrict__ biasor)
{
    __shared__ float xs[1024];
    int t = blockIdx.x;
    int tid = threadIdx.x;   // 256
#pragma unroll
    for (int i = tid; i < 1024; i += 256) xs[i] = X[t * 1024 + i];
    __syncthreads();

    int o = tid & 31, w = tid >> 5;
    const __half* Mrow = Mbuf + (size_t)t * D_BIG;
#pragma unroll
    for (int gi = 0; gi < 4; gi++) {
        int g = w * 4 + gi;
        float acc = 0.0f;
        const __half* mp = Mrow + g * 1024 + o;
#pragma unroll
        for (int i = 0; i < 32; i++) acc += xs[g * 32 + i] * __half2float(mp[i * 32]);
        if (STAGE == 1) {
            out[t * 1024 + o * 32 + g] = acc;           // transposed for stage 2
        } else {
            int idx = t * 1024 + g * 32 + o;
            out[idx] = acc * ratio[t] + biasor[idx];
        }
    }
}

// ---------------------------------------------------------------------------
extern "C" void kernel_launch(void* const* d_in, const int* in_sizes, int n_in,
                              void* d_out, int out_size)
{
    const float* x   = (const float*)d_in[0];
    const float* Wc  = (const float*)d_in[1];
    const float* bc  = (const float*)d_in[2];
    const float* W1a = (const float*)d_in[3];
    const float* b1a = (const float*)d_in[4];
    const float* W1b = (const float*)d_in[5];
    const float* b1b = (const float*)d_in[6];
    const float* W2a = (const float*)d_in[7];
    const float* b2a = (const float*)d_in[8];
    const float* W2b = (const float*)d_in[9];
    const float* b2b = (const float*)d_in[10];
    const float* Wm1 = (const float*)d_in[11];
    const float* bm1 = (const float*)d_in[12];
    const float* Wm2 = (const float*)d_in[13];
    const float* bm2 = (const float*)d_in[14];
    const float* Wb  = (const float*)d_in[15];
    const float* bb  = (const float*)d_in[16];
    const float* Wr  = (const float*)d_in[17];
    const float* br  = (const float*)d_in[18];
    float* out = (float*)d_out;

    float *p_c, *p_co, *p_ra, *p_bi, *p_x1;
    __half *p_a, *p_b, *p_M, *p_w16;
    cudaGetSymbolAddress((void**)&p_c,   g_c);
    cudaGetSymbolAddress((void**)&p_a,   g_A16a);
    cudaGetSymbolAddress((void**)&p_b,   g_A16b);
    cudaGetSymbolAddress((void**)&p_co,  g_coeffs);
    cudaGetSymbolAddress((void**)&p_ra,  g_ratio);
    cudaGetSymbolAddress((void**)&p_bi,  g_biasor);
    cudaGetSymbolAddress((void**)&p_x1,  g_x1oT);
    cudaGetSymbolAddress((void**)&p_M,   g_M);
    cudaGetSymbolAddress((void**)&p_w16, g_W16);

    static bool attr_done = false;
    if (!attr_done) {
        cudaFuncSetAttribute(bgemm_half,
                             cudaFuncAttributeMaxDynamicSharedMemorySize,
                             BGEMM_SMEM);
        attr_done = true;
    }

    // 0. W1b/W2b fp32 -> fp16
    convert_w<<<dim3(16384, 2), 256>>>(W1b, W2b, p_w16);

    // 1. c = silu(x @ Wc + bc)
    sgemm_c<<<dim3(C_DIM / 64, T_TOK / 64), 256>>>(x, Wc, p_c, bc);

    // 2. coeffs (softmax), ratio
    mixer_kernel<<<T_TOK, C_DIM>>>(p_c, Wm1, bm1, Wm2, bm2, Wr, br, p_co, p_ra);

    // 3. expert-gens (both stages) + biasor, ONE launch (z=0..7 gen, z=8 biasor)
    gen_all<<<dim3(16, T_TOK / 64, 9), 256>>>(
        p_c, W1a, b1a, W2a, b2a, Wb, bb, p_co, p_a, p_b, p_bi);

    // 4. merged bgemm (z picks stage), 2 CTAs/SM
    bgemm_half<<<dim3(T_TOK / 128, D_BIG / 128, 2), 256, BGEMM_SMEM>>>(
        p_a, p_b, p_w16, p_M, b1b, b2b, p_co);

    // 5. Monarch stage 1 (writes transposed)
    monarch_kernel<1><<<T_TOK, 256>>>(x, p_M, p_x1, nullptr, nullptr);

    // 6. Monarch stage 2 + final epilogue
    monarch_kernel<2><<<T_TOK, 256>>>(
        p_x1, p_M + (size_t)T_TOK * D_BIG, out, p_ra, p_bi);
}

// round 13
// speedup vs baseline: 1.4988x; 1.1065x over previous
#include <cuda_runtime.h>
#include <cuda_bf16.h>
#include <cuda_fp16.h>
#include <cstdint>
#include <cstddef>

// ---------------------------------------------------------------------------
// HyperMoMixLinear on GB300 (sm_103a harness, PLAIN sm_103 ptx target).
// bgemm (mma.sync fp16, 1-term, 2 CTAs/SM) measured at the legacy-HMMA pipe
// floor (~16.7 cyc/MMA/SMSP). R13: hide convert_w (65us, DRAM-bound, no deps)
// inside the latency-bound small kernels via FAT KERNELS (block-range split
// within single launches; stream forks measured to cost ~100us here).
// ---------------------------------------------------------------------------

#define T_TOK 512
#define C_DIM 256
#define IN_DIM 1024
#define OUT_DIM 1024
#define K_EXP 4
#define D_BIG 32768
#define KC 1024   // K_EXP * C_DIM  == GEMM K
#define W_ELEMS ((size_t)KC * D_BIG)

// convert work: 16384 chunks per weight, 32768 total; split across 3 launches
#define CV1 12288
#define CV2 4096
#define CV3 16384   // CV1+CV2+CV3 == 32768

// -------------------- device scratch (no runtime allocation) ---------------
__device__ float g_c[T_TOK * C_DIM];
__device__ __half g_A16a[T_TOK * KC];
__device__ __half g_A16b[T_TOK * KC];
__device__ float g_coeffs[T_TOK * K_EXP];
__device__ float g_ratio[T_TOK];
__device__ float g_biasor[T_TOK * OUT_DIM];
__device__ float g_x1oT[T_TOK * OUT_DIM];          // stage-1 out, transposed
__device__ __half g_M[2 * (size_t)T_TOK * D_BIG];  // 2 x 32 MB (M1, M2)
__device__ __half g_W16[2 * W_ELEMS];              // 128 MB fp16 weights

__device__ __forceinline__ float silu_f(float v) {
    return v / (1.0f + __expf(-v));
}

__device__ __forceinline__ uint32_t smem_u32(const void* p) {
    uint32_t a;
    asm("{ .reg .u64 t; cvta.to.shared.u64 t, %1; cvt.u32.u64 %0, t; }"
        : "=r"(a) : "l"(p));
    return a;
}

#define CP_ASYNC16(dst, src) \
    asm volatile("cp.async.cg.shared.global [%0], [%1], 16;" \
                 :: "r"(dst), "l"(src) : "memory")
#define CP_COMMIT() asm volatile("cp.async.commit_group;" ::: "memory")
#define CP_WAIT0()  asm volatile("cp.async.wait_group 0;" ::: "memory")

#define LDSM4(r, addr) \
    asm volatile("ldmatrix.sync.aligned.m8n8.x4.shared.b16 {%0,%1,%2,%3}, [%4];" \
        : "=r"((r)[0]), "=r"((r)[1]), "=r"((r)[2]), "=r"((r)[3]) : "r"(addr))
#define LDSM4T(r, addr) \
    asm volatile("ldmatrix.sync.aligned.m8n8.x4.trans.shared.b16 {%0,%1,%2,%3}, [%4];" \
        : "=r"((r)[0]), "=r"((r)[1]), "=r"((r)[2]), "=r"((r)[3]) : "r"(addr))

#define MMA_F16(d, a, b0v, b1v) \
    asm volatile("mma.sync.aligned.m16n8k16.row.col.f32.f16.f16.f32 " \
        "{%0,%1,%2,%3}, {%4,%5,%6,%7}, {%8,%9}, {%0,%1,%2,%3};" \
        : "+f"((d)[0]), "+f"((d)[1]), "+f"((d)[2]), "+f"((d)[3]) \
        : "r"((a)[0]), "r"((a)[1]), "r"((a)[2]), "r"((a)[3]), \
          "r"(b0v), "r"(b1v))

// -------------------- convert chunk (one block's share) --------------------
// cb in [0, 32768): cb < 16384 -> W1b chunk, else W2b chunk. 2048 elems/block.
__device__ __forceinline__ void convert_chunk(int cb,
                                              const float* __restrict__ W1b,
                                              const float* __restrict__ W2b,
                                              __half* __restrict__ W16)
{
    const float* W = (cb >= 16384) ? W2b : W1b;
    __half* dst = W16 + ((cb >= 16384) ? W_ELEMS : 0);
    int b = cb & 16383;
    size_t base = ((size_t)b * 256 + threadIdx.x) * 8;
    float4 v0 = *(const float4*)(W + base);
    float4 v1 = *(const float4*)(W + base + 4);
    __half2 h0 = __floats2half2_rn(v0.x, v0.y);
    __half2 h1 = __floats2half2_rn(v0.z, v0.w);
    __half2 h2 = __floats2half2_rn(v1.x, v1.y);
    __half2 h3 = __floats2half2_rn(v1.z, v1.w);
    uint4 o;
    o.x = *(uint32_t*)&h0; o.y = *(uint32_t*)&h1;
    o.z = *(uint32_t*)&h2; o.w = *(uint32_t*)&h3;
    *(uint4*)(dst + base) = o;
}

// -------------------- L1: compressor GEMM + convert chunk ------------------
// grid (32 + CV1): bx<32 -> c = silu(x @ Wc + bc) tile; else convert.
__global__ void k1_c_conv(const float* __restrict__ x, const float* __restrict__ Wc,
                          float* __restrict__ c, const float* __restrict__ bc,
                          const float* __restrict__ W1b, const float* __restrict__ W2b,
                          __half* __restrict__ W16)
{
    int bx = blockIdx.x;
    if (bx >= 32) { convert_chunk(bx - 32, W1b, W2b, W16); return; }

    const int BM = 64, BN = 64, BK = 16;
    __shared__ float As[BK][BM];
    __shared__ float Bs[BK][BN];
    int tid = threadIdx.x;
    int m0 = (bx >> 2) * BM;
    int n0 = (bx & 3) * BN;
    int tx = tid % 16, ty = tid / 16;
    int arow = tid / 4, aq = tid % 4;
    int brow = tid / 16, bq = tid % 16;
    float acc[4][4] = {};

    for (int k0 = 0; k0 < IN_DIM; k0 += BK) {
        float4 av = *(const float4*)&x[(m0 + arow) * IN_DIM + k0 + aq * 4];
        As[aq * 4 + 0][arow] = av.x;
        As[aq * 4 + 1][arow] = av.y;
        As[aq * 4 + 2][arow] = av.z;
        As[aq * 4 + 3][arow] = av.w;
        *(float4*)&Bs[brow][bq * 4] =
            *(const float4*)&Wc[(k0 + brow) * C_DIM + n0 + bq * 4];
        __syncthreads();
#pragma unroll
        for (int k = 0; k < BK; k++) {
            float a[4], b[4];
#pragma unroll
            for (int i = 0; i < 4; i++) a[i] = As[k][ty * 4 + i];
#pragma unroll
            for (int j = 0; j < 4; j++) b[j] = Bs[k][tx * 4 + j];
#pragma unroll
            for (int i = 0; i < 4; i++)
#pragma unroll
                for (int j = 0; j < 4; j++) acc[i][j] += a[i] * b[j];
        }
        __syncthreads();
    }

#pragma unroll
    for (int i = 0; i < 4; i++) {
        int m = m0 + ty * 4 + i;
#pragma unroll
        for (int j = 0; j < 4; j++) {
            int n = n0 + tx * 4 + j;
            c[m * C_DIM + n] = silu_f(acc[i][j] + bc[n]);
        }
    }
}

// -------------------- L2: mixer + convert chunk ----------------------------
// grid (512 + CV2): bx<512 -> mixer token; else convert (offset CV1).
__global__ void k2_mix_conv(const float* __restrict__ c,
                            const float* __restrict__ Wm1, const float* __restrict__ bm1,
                            const float* __restrict__ Wm2, const float* __restrict__ bm2,
                            const float* __restrict__ Wr,  const float* __restrict__ br,
                            float* __restrict__ coeffs, float* __restrict__ ratio,
                            const float* __restrict__ W1b, const float* __restrict__ W2b,
                            __half* __restrict__ W16)
{
    int bx = blockIdx.x;
    if (bx >= 512) { convert_chunk(bx - 512 + CV1, W1b, W2b, W16); return; }

    __shared__ float cs[C_DIM];
    __shared__ float ms[C_DIM];
    __shared__ float red[C_DIM];
    __shared__ float lg[K_EXP];
    int t = bx, tid = threadIdx.x;

    cs[tid] = c[t * C_DIM + tid];
    __syncthreads();

    float acc = bm1[tid];
#pragma unroll 8
    for (int i = 0; i < C_DIM; i++) acc += cs[i] * Wm1[i * C_DIM + tid];
    ms[tid] = silu_f(acc);
    red[tid] = cs[tid] * Wr[tid];
    __syncthreads();

    if (tid < K_EXP) {
        float l = bm2[tid];
#pragma unroll 8
        for (int i = 0; i < C_DIM; i++) l += ms[i] * Wm2[i * K_EXP + tid];
        lg[tid] = l;
    }
    for (int s = 128; s > 0; s >>= 1) {
        __syncthreads();
        if (tid < s) red[tid] += red[tid + s];
    }
    __syncthreads();

    if (tid == 0) {
        ratio[t] = red[0] + br[0];
        float mx = fmaxf(fmaxf(lg[0], lg[1]), fmaxf(lg[2], lg[3]));
        float e0 = __expf(lg[0] - mx), e1 = __expf(lg[1] - mx);
        float e2 = __expf(lg[2] - mx), e3 = __expf(lg[3] - mx);
        float inv = 1.0f / (e0 + e1 + e2 + e3);
        coeffs[t * 4 + 0] = e0 * inv;
        coeffs[t * 4 + 1] = e1 * inv;
        coeffs[t * 4 + 2] = e2 * inv;
        coeffs[t * 4 + 3] = e3 * inv;
    }
}

// -------------------- L3: expert-gens + biasor + convert chunk -------------
// grid (384 + CV3):
//   bx < 256: expert-gen (z = bx>>5 in [0,8), tile r = bx&31: n0=(r&3), m0=(r>>2))
//   bx in [256,384): biasor tile (r = bx-256: n0=(r&15), m0=(r>>4))
//   else: convert (offset CV1+CV2)
__global__ void k3_gen_conv(const float* __restrict__ c,
                            const float* __restrict__ W1a, const float* __restrict__ b1a,
                            const float* __restrict__ W2a, const float* __restrict__ b2a,
                            const float* __restrict__ Wb,  const float* __restrict__ bb,
                            const float* __restrict__ coeffs,
                            __half* __restrict__ g16a, __half* __restrict__ g16b,
                            float* __restrict__ biasor,
                            const float* __restrict__ W1b, const float* __restrict__ W2b,
                            __half* __restrict__ W16)
{
    int bx = blockIdx.x;
    if (bx >= 384) { convert_chunk(bx - 384 + CV1 + CV2, W1b, W2b, W16); return; }

    const int BM = 64, BN = 64, BK = 16;
    bool isB = (bx >= 256);
    const float* B;
    const float* bias;
    __half* g16 = nullptr;
    int ldb, kz = 0, m0, n0;
    if (isB) {
        int r = bx - 256;
        n0 = (r & 15) * BN; m0 = (r >> 4) * BM;
        B = Wb; bias = bb; ldb = OUT_DIM;
    } else {
        int z = bx >> 5, r = bx & 31;
        kz = z & 3;
        n0 = (r & 3) * BN; m0 = (r >> 2) * BM;
        B = (z < 4 ? W1a : W2a) + (long)kz * C_DIM * C_DIM;
        bias = (z < 4 ? b1a : b2a) + kz * C_DIM;
        g16 = (z < 4 ? g16a : g16b);
        ldb = C_DIM;
    }

    __shared__ float As[BK][BM];
    __shared__ float Bs[BK][BN];
    int tid = threadIdx.x;
    int tx = tid % 16, ty = tid / 16;
    int arow = tid / 4, aq = tid % 4;
    int brow = tid / 16, bq = tid % 16;
    float acc[4][4] = {};

    for (int k0 = 0; k0 < C_DIM; k0 += BK) {
        float4 av = *(const float4*)&c[(m0 + arow) * C_DIM + k0 + aq * 4];
        As[aq * 4 + 0][arow] = av.x;
        As[aq * 4 + 1][arow] = av.y;
        As[aq * 4 + 2][arow] = av.z;
        As[aq * 4 + 3][arow] = av.w;
        *(float4*)&Bs[brow][bq * 4] =
            *(const float4*)&B[(k0 + brow) * ldb + n0 + bq * 4];
        __syncthreads();
#pragma unroll
        for (int k = 0; k < BK; k++) {
            float a[4], b[4];
#pragma unroll
            for (int i = 0; i < 4; i++) a[i] = As[k][ty * 4 + i];
#pragma unroll
            for (int j = 0; j < 4; j++) b[j] = Bs[k][tx * 4 + j];
#pragma unroll
            for (int i = 0; i < 4; i++)
#pragma unroll
                for (int j = 0; j < 4; j++) acc[i][j] += a[i] * b[j];
        }
        __syncthreads();
    }

#pragma unroll
    for (int i = 0; i < 4; i++) {
        int m = m0 + ty * 4 + i;
        float cf = isB ? 1.0f : coeffs[m * K_EXP + kz];
#pragma unroll
        for (int j = 0; j < 4; j++) {
            int n = n0 + tx * 4 + j;
            float v = acc[i][j] + bias[n];
            if (isB) {
                biasor[m * OUT_DIM + n] = v;
            } else {
                v = cf * silu_f(v);
                g16[m * KC + kz * C_DIM + n] = __float2half(v);
            }
        }
    }
}

// -------------------- big GEMM on mma.sync (fp16, both operands cp.async) --
// z = blockIdx.z picks (A16, W16 plane, bB, Mout plane). Merged launch.
// NSTG=2 (64 KB smem) -> 2 CTAs/SM; one-sync issue-ahead loop.
#define STG_SZ 32768
#define B_OFF 16384
#define NSTG 2
#define BGEMM_SMEM (NSTG * STG_SZ)   // 64 KB

__global__ void __launch_bounds__(256, 2) bgemm_half(
    const __half* __restrict__ A16a, const __half* __restrict__ A16b,
    const __half* __restrict__ W16,
    __half* __restrict__ Mbuf,
    const float* __restrict__ bB1, const float* __restrict__ bB2,
    const float* __restrict__ coeffs)
{
    extern __shared__ __align__(128) char smem[];
    const uint32_t sbase = smem_u32(smem);
    const int tid = threadIdx.x, wid = tid >> 5, lane = tid & 31;
    const int m0 = blockIdx.x * 128, n0 = blockIdx.y * 128;
    const int z = blockIdx.z;
    const int warp_m = wid & 1, warp_n = wid >> 1;

    const __half* A16 = z ? A16b : A16a;
    const __half* W = W16 + (size_t)z * W_ELEMS;
    const float* bB = z ? bB2 : bB1;
    __half* Mout = Mbuf + (size_t)z * T_TOK * D_BIG;

    float acc[4][4][4] = {};

    const int a_m = tid >> 2;
    const int a_q = tid & 3;
    const int b_k = tid >> 2;
    const int b_cq = tid & 3;

    const int aRow = warp_m * 64 + (lane & 15);
    const uint32_t axor = ((uint32_t)(aRow & 7)) << 4;
    const uint32_t aKhalf = ((lane >> 4) & 1) * 16;
    uint32_t kOff[4];
#pragma unroll
    for (int ks = 0; ks < 4; ks++)
        kOff[ks] = ((uint32_t)(ks * 32) + aKhalf) ^ axor;
    const uint32_t aBase = (uint32_t)aRow * 128;

    const int kLoc = (lane & 7) | (((lane >> 3) & 1) << 3);
    const uint32_t bxor = ((uint32_t)(kLoc & 7)) << 4;
    const uint32_t bBase = (uint32_t)kLoc * 256;
    uint32_t nbp[2];
#pragma unroll
    for (int p = 0; p < 2; p++)
        nbp[p] = ((uint32_t)((warp_n * 32 + p * 16 + ((lane >> 4) & 1) * 8) * 2)) ^ bxor;

    auto issue = [&](int it, int buf) {
        uint32_t s = sbase + buf * STG_SZ;
        int k0 = it * 64;
#pragma unroll
        for (int i = 0; i < 4; i++) {
            int m = a_m + (i & 1) * 64;
            int q = a_q + (i >> 1) * 4;
            const __half* src = A16 + (size_t)(m0 + m) * KC + k0 + q * 8;
            uint32_t dst = s + (uint32_t)m * 128 +
                           (((uint32_t)(q * 16)) ^ (((uint32_t)(m & 7)) << 4));
            CP_ASYNC16(dst, src);
        }
#pragma unroll
        for (int i = 0; i < 4; i++) {
            int chunk = b_cq + i * 4;
            const __half* src = W + (size_t)(k0 + b_k) * D_BIG + n0 + chunk * 8;
            uint32_t dst = s + B_OFF + (uint32_t)b_k * 256 +
                           (((uint32_t)(chunk * 16)) ^ (((uint32_t)(b_k & 7)) << 4));
            CP_ASYNC16(dst, src);
        }
        CP_COMMIT();
    };
    auto mmaStage = [&](int buf) {
        uint32_t sA = sbase + buf * STG_SZ;
        uint32_t sB = sA + B_OFF;
#pragma unroll
        for (int ks = 0; ks < 4; ks++) {
            uint32_t ah[4][4], bb[2][4];
#pragma unroll
            for (int mt = 0; mt < 4; mt++)
                LDSM4(ah[mt], sA + aBase + mt * 2048 + kOff[ks]);
#pragma unroll
            for (int p = 0; p < 2; p++)
                LDSM4T(bb[p], sB + ks * 4096 + bBase + nbp[p]);
#pragma unroll
            for (int mt = 0; mt < 4; mt++)
#pragma unroll
                for (int nt = 0; nt < 4; nt++)
                    MMA_F16(acc[mt][nt], ah[mt],
                            bb[nt >> 1][(nt & 1) * 2], bb[nt >> 1][(nt & 1) * 2 + 1]);
        }
    };

    issue(0, 0);
    CP_WAIT0();
    __syncthreads();

    for (int it = 0; it < 16; ++it) {
        int cur = it & 1, nxt = cur ^ 1;
        if (it < 15) issue(it + 1, nxt);
        mmaStage(cur);
        CP_WAIT0();
        __syncthreads();
    }

    const int mw = m0 + warp_m * 64;
    const int nw = n0 + warp_n * 32;
    const int row = lane >> 2, colq = (lane & 3) * 2;
#pragma unroll
    for (int nt = 0; nt < 4; nt++) {
        int n = nw + nt * 8 + colq;
        float bv[K_EXP][2];
#pragma unroll
        for (int e = 0; e < K_EXP; e++) {
            bv[e][0] = bB[(size_t)e * D_BIG + n];
            bv[e][1] = bB[(size_t)e * D_BIG + n + 1];
        }
#pragma unroll
        for (int mt = 0; mt < 4; mt++) {
            int m = mw + mt * 16 + row;
            float4 c0 = *(const float4*)(coeffs + m * 4);
            float4 c1 = *(const float4*)(coeffs + (m + 8) * 4);
            float b00 = c0.x * bv[0][0] + c0.y * bv[1][0] + c0.z * bv[2][0] + c0.w * bv[3][0];
            float b01 = c0.x * bv[0][1] + c0.y * bv[1][1] + c0.z * bv[2][1] + c0.w * bv[3][1];
            float b10 = c1.x * bv[0][0] + c1.y * bv[1][0] + c1.z * bv[2][0] + c1.w * bv[3][0];
            float b11 = c1.x * bv[0][1] + c1.y * bv[1][1] + c1.z * bv[2][1] + c1.w * bv[3][1];
            __half2 h0 = __floats2half2_rn(acc[mt][nt][0] + b00, acc[mt][nt][1] + b01);
            __half2 h1 = __floats2half2_rn(acc[mt][nt][2] + b10, acc[mt][nt][3] + b11);
            *(__half2*)(Mout + (size_t)m * D_BIG + n) = h0;
            *(__half2*)(Mout + (size_t)(m + 8) * D_BIG + n) = h1;
        }
    }
}

// -------------------- Monarch stage: per-(token,g) 32x32 GEMV (fp16 M) -----
template<int STAGE>
__global__ void monarch_kernel(const float* __restrict__ X,
                               const __half* __restrict__ Mbuf,
                               float* __restrict__ out,
                               const float* __restrict__ ratio,
                               const float* __restrict__ biasor)
{
    __shared__ float xs[1024];
    int t = blockIdx.x;
    int tid = threadIdx.x;   // 256
#pragma unroll
    for (int i = tid; i < 1024; i += 256) xs[i] = X[t * 1024 + i];
    __syncthreads();

    int o = tid & 31, w = tid >> 5;
    const __half* Mrow = Mbuf + (size_t)t * D_BIG;
#pragma unroll
    for (int gi = 0; gi < 4; gi++) {
        int g = w * 4 + gi;
        float acc = 0.0f;
        const __half* mp = Mrow + g * 1024 + o;
#pragma unroll
        for (int i = 0; i < 32; i++) acc += xs[g * 32 + i] * __half2float(mp[i * 32]);
        if (STAGE == 1) {
            out[t * 1024 + o * 32 + g] = acc;           // transposed for stage 2
        } else {
            int idx = t * 1024 + g * 32 + o;
            out[idx] = acc * ratio[t] + biasor[idx];
        }
    }
}

// ---------------------------------------------------------------------------
extern "C" void kernel_launch(void* const* d_in, const int* in_sizes, int n_in,
                              void* d_out, int out_size)
{
    const float* x   = (const float*)d_in[0];
    const float* Wc  = (const float*)d_in[1];
    const float* bc  = (const float*)d_in[2];
    const float* W1a = (const float*)d_in[3];
    const float* b1a = (const float*)d_in[4];
    const float* W1b = (const float*)d_in[5];
    const float* b1b = (const float*)d_in[6];
    const float* W2a = (const float*)d_in[7];
    const float* b2a = (const float*)d_in[8];
    const float* W2b = (const float*)d_in[9];
    const float* b2b = (const float*)d_in[10];
    const float* Wm1 = (const float*)d_in[11];
    const float* bm1 = (const float*)d_in[12];
    const float* Wm2 = (const float*)d_in[13];
    const float* bm2 = (const float*)d_in[14];
    const float* Wb  = (const float*)d_in[15];
    const float* bb  = (const float*)d_in[16];
    const float* Wr  = (const float*)d_in[17];
    const float* br  = (const float*)d_in[18];
    float* out = (float*)d_out;

    float *p_c, *p_co, *p_ra, *p_bi, *p_x1;
    __half *p_a, *p_b, *p_M, *p_w16;
    cudaGetSymbolAddress((void**)&p_c,   g_c);
    cudaGetSymbolAddress((void**)&p_a,   g_A16a);
    cudaGetSymbolAddress((void**)&p_b,   g_A16b);
    cudaGetSymbolAddress((void**)&p_co,  g_coeffs);
    cudaGetSymbolAddress((void**)&p_ra,  g_ratio);
    cudaGetSymbolAddress((void**)&p_bi,  g_biasor);
    cudaGetSymbolAddress((void**)&p_x1,  g_x1oT);
    cudaGetSymbolAddress((void**)&p_M,   g_M);
    cudaGetSymbolAddress((void**)&p_w16, g_W16);

    static bool attr_done = false;
    if (!attr_done) {
        cudaFuncSetAttribute(bgemm_half,
                             cudaFuncAttributeMaxDynamicSharedMemorySize,
                             BGEMM_SMEM);
        attr_done = true;
    }

    // L1: c = silu(x @ Wc + bc)  +  convert chunk 1
    k1_c_conv<<<32 + CV1, 256>>>(x, Wc, p_c, bc, W1b, W2b, p_w16);

    // L2: coeffs/ratio  +  convert chunk 2
    k2_mix_conv<<<512 + CV2, 256>>>(p_c, Wm1, bm1, Wm2, bm2, Wr, br,
                                    p_co, p_ra, W1b, W2b, p_w16);

    // L3: expert-gens (both stages) + biasor  +  convert chunk 3
    k3_gen_conv<<<384 + CV3, 256>>>(p_c, W1a, b1a, W2a, b2a, Wb, bb, p_co,
                                    p_a, p_b, p_bi, W1b, W2b, p_w16);

    // merged bgemm (z picks stage), 2 CTAs/SM
    bgemm_half<<<dim3(T_TOK / 128, D_BIG / 128, 2), 256, BGEMM_SMEM>>>(
        p_a, p_b, p_w16, p_M, b1b, b2b, p_co);

    // Monarch stage 1 (writes transposed)
    monarch_kernel<1><<<T_TOK, 256>>>(x, p_M, p_x1, nullptr, nullptr);

    // Monarch stage 2 + final epilogue
    monarch_kernel<2><<<T_TOK, 256>>>(
        p_x1, p_M + (size_t)T_TOK * D_BIG, out, p_ra, p_bi);
}

// round 14
// speedup vs baseline: 1.5145x; 1.0105x over previous
#include <cuda_runtime.h>
#include <cuda_bf16.h>
#include <cuda_fp16.h>
#include <cstdint>
#include <cstddef>

// ---------------------------------------------------------------------------
// HyperMoMixLinear on GB300 (sm_103a harness, PLAIN sm_103 ptx target).
// R14: bgemm ncu showed tensor=57.9% with a full cp.async drain (wait_group 0)
// every iteration. Switch to a 3-stage ring + wait_group 1 so one load stays
// in flight across each mma stage; still 2 CTAs/SM (96 KB smem).
// Everything outside bgemm identical to R13 (fat-kernel convert overlap).
// ---------------------------------------------------------------------------

#define T_TOK 512
#define C_DIM 256
#define IN_DIM 1024
#define OUT_DIM 1024
#define K_EXP 4
#define D_BIG 32768
#define KC 1024   // K_EXP * C_DIM  == GEMM K
#define W_ELEMS ((size_t)KC * D_BIG)

// convert work: 16384 chunks per weight, 32768 total; split across 3 launches
#define CV1 12288
#define CV2 4096
#define CV3 16384   // CV1+CV2+CV3 == 32768

// -------------------- device scratch (no runtime allocation) ---------------
__device__ float g_c[T_TOK * C_DIM];
__device__ __half g_A16a[T_TOK * KC];
__device__ __half g_A16b[T_TOK * KC];
__device__ float g_coeffs[T_TOK * K_EXP];
__device__ float g_ratio[T_TOK];
__device__ float g_biasor[T_TOK * OUT_DIM];
__device__ float g_x1oT[T_TOK * OUT_DIM];          // stage-1 out, transposed
__device__ __half g_M[2 * (size_t)T_TOK * D_BIG];  // 2 x 32 MB (M1, M2)
__device__ __half g_W16[2 * W_ELEMS];              // 128 MB fp16 weights

__device__ __forceinline__ float silu_f(float v) {
    return v / (1.0f + __expf(-v));
}

__device__ __forceinline__ uint32_t smem_u32(const void* p) {
    uint32_t a;
    asm("{ .reg .u64 t; cvta.to.shared.u64 t, %1; cvt.u32.u64 %0, t; }"
        : "=r"(a) : "l"(p));
    return a;
}

#define CP_ASYNC16(dst, src) \
    asm volatile("cp.async.cg.shared.global [%0], [%1], 16;" \
                 :: "r"(dst), "l"(src) : "memory")
#define CP_COMMIT() asm volatile("cp.async.commit_group;" ::: "memory")
#define CP_WAIT0()  asm volatile("cp.async.wait_group 0;" ::: "memory")
#define CP_WAIT1()  asm volatile("cp.async.wait_group 1;" ::: "memory")

#define LDSM4(r, addr) \
    asm volatile("ldmatrix.sync.aligned.m8n8.x4.shared.b16 {%0,%1,%2,%3}, [%4];" \
        : "=r"((r)[0]), "=r"((r)[1]), "=r"((r)[2]), "=r"((r)[3]) : "r"(addr))
#define LDSM4T(r, addr) \
    asm volatile("ldmatrix.sync.aligned.m8n8.x4.trans.shared.b16 {%0,%1,%2,%3}, [%4];" \
        : "=r"((r)[0]), "=r"((r)[1]), "=r"((r)[2]), "=r"((r)[3]) : "r"(addr))

#define MMA_F16(d, a, b0v, b1v) \
    asm volatile("mma.sync.aligned.m16n8k16.row.col.f32.f16.f16.f32 " \
        "{%0,%1,%2,%3}, {%4,%5,%6,%7}, {%8,%9}, {%0,%1,%2,%3};" \
        : "+f"((d)[0]), "+f"((d)[1]), "+f"((d)[2]), "+f"((d)[3]) \
        : "r"((a)[0]), "r"((a)[1]), "r"((a)[2]), "r"((a)[3]), \
          "r"(b0v), "r"(b1v))

// -------------------- convert chunk (one block's share) --------------------
// cb in [0, 32768): cb < 16384 -> W1b chunk, else W2b chunk. 2048 elems/block.
__device__ __forceinline__ void convert_chunk(int cb,
                                              const float* __restrict__ W1b,
                                              const float* __restrict__ W2b,
                                              __half* __restrict__ W16)
{
    const float* W = (cb >= 16384) ? W2b : W1b;
    __half* dst = W16 + ((cb >= 16384) ? W_ELEMS : 0);
    int b = cb & 16383;
    size_t base = ((size_t)b * 256 + threadIdx.x) * 8;
    float4 v0 = *(const float4*)(W + base);
    float4 v1 = *(const float4*)(W + base + 4);
    __half2 h0 = __floats2half2_rn(v0.x, v0.y);
    __half2 h1 = __floats2half2_rn(v0.z, v0.w);
    __half2 h2 = __floats2half2_rn(v1.x, v1.y);
    __half2 h3 = __floats2half2_rn(v1.z, v1.w);
    uint4 o;
    o.x = *(uint32_t*)&h0; o.y = *(uint32_t*)&h1;
    o.z = *(uint32_t*)&h2; o.w = *(uint32_t*)&h3;
    *(uint4*)(dst + base) = o;
}

// -------------------- L1: compressor GEMM + convert chunk ------------------
__global__ void k1_c_conv(const float* __restrict__ x, const float* __restrict__ Wc,
                          float* __restrict__ c, const float* __restrict__ bc,
                          const float* __restrict__ W1b, const float* __restrict__ W2b,
                          __half* __restrict__ W16)
{
    int bx = blockIdx.x;
    if (bx >= 32) { convert_chunk(bx - 32, W1b, W2b, W16); return; }

    const int BM = 64, BN = 64, BK = 16;
    __shared__ float As[BK][BM];
    __shared__ float Bs[BK][BN];
    int tid = threadIdx.x;
    int m0 = (bx >> 2) * BM;
    int n0 = (bx & 3) * BN;
    int tx = tid % 16, ty = tid / 16;
    int arow = tid / 4, aq = tid % 4;
    int brow = tid / 16, bq = tid % 16;
    float acc[4][4] = {};

    for (int k0 = 0; k0 < IN_DIM; k0 += BK) {
        float4 av = *(const float4*)&x[(m0 + arow) * IN_DIM + k0 + aq * 4];
        As[aq * 4 + 0][arow] = av.x;
        As[aq * 4 + 1][arow] = av.y;
        As[aq * 4 + 2][arow] = av.z;
        As[aq * 4 + 3][arow] = av.w;
        *(float4*)&Bs[brow][bq * 4] =
            *(const float4*)&Wc[(k0 + brow) * C_DIM + n0 + bq * 4];
        __syncthreads();
#pragma unroll
        for (int k = 0; k < BK; k++) {
            float a[4], b[4];
#pragma unroll
            for (int i = 0; i < 4; i++) a[i] = As[k][ty * 4 + i];
#pragma unroll
            for (int j = 0; j < 4; j++) b[j] = Bs[k][tx * 4 + j];
#pragma unroll
            for (int i = 0; i < 4; i++)
#pragma unroll
                for (int j = 0; j < 4; j++) acc[i][j] += a[i] * b[j];
        }
        __syncthreads();
    }

#pragma unroll
    for (int i = 0; i < 4; i++) {
        int m = m0 + ty * 4 + i;
#pragma unroll
        for (int j = 0; j < 4; j++) {
            int n = n0 + tx * 4 + j;
            c[m * C_DIM + n] = silu_f(acc[i][j] + bc[n]);
        }
    }
}

// -------------------- L2: mixer + convert chunk ----------------------------
__global__ void k2_mix_conv(const float* __restrict__ c,
                            const float* __restrict__ Wm1, const float* __restrict__ bm1,
                            const float* __restrict__ Wm2, const float* __restrict__ bm2,
                            const float* __restrict__ Wr,  const float* __restrict__ br,
                            float* __restrict__ coeffs, float* __restrict__ ratio,
                            const float* __restrict__ W1b, const float* __restrict__ W2b,
                            __half* __restrict__ W16)
{
    int bx = blockIdx.x;
    if (bx >= 512) { convert_chunk(bx - 512 + CV1, W1b, W2b, W16); return; }

    __shared__ float cs[C_DIM];
    __shared__ float ms[C_DIM];
    __shared__ float red[C_DIM];
    __shared__ float lg[K_EXP];
    int t = bx, tid = threadIdx.x;

    cs[tid] = c[t * C_DIM + tid];
    __syncthreads();

    float acc = bm1[tid];
#pragma unroll 8
    for (int i = 0; i < C_DIM; i++) acc += cs[i] * Wm1[i * C_DIM + tid];
    ms[tid] = silu_f(acc);
    red[tid] = cs[tid] * Wr[tid];
    __syncthreads();

    if (tid < K_EXP) {
        float l = bm2[tid];
#pragma unroll 8
        for (int i = 0; i < C_DIM; i++) l += ms[i] * Wm2[i * K_EXP + tid];
        lg[tid] = l;
    }
    for (int s = 128; s > 0; s >>= 1) {
        __syncthreads();
        if (tid < s) red[tid] += red[tid + s];
    }
    __syncthreads();

    if (tid == 0) {
        ratio[t] = red[0] + br[0];
        float mx = fmaxf(fmaxf(lg[0], lg[1]), fmaxf(lg[2], lg[3]));
        float e0 = __expf(lg[0] - mx), e1 = __expf(lg[1] - mx);
        float e2 = __expf(lg[2] - mx), e3 = __expf(lg[3] - mx);
        float inv = 1.0f / (e0 + e1 + e2 + e3);
        coeffs[t * 4 + 0] = e0 * inv;
        coeffs[t * 4 + 1] = e1 * inv;
        coeffs[t * 4 + 2] = e2 * inv;
        coeffs[t * 4 + 3] = e3 * inv;
    }
}

// -------------------- L3: expert-gens + biasor + convert chunk -------------
__global__ void k3_gen_conv(const float* __restrict__ c,
                            const float* __restrict__ W1a, const float* __restrict__ b1a,
                            const float* __restrict__ W2a, const float* __restrict__ b2a,
                            const float* __restrict__ Wb,  const float* __restrict__ bb,
                            const float* __restrict__ coeffs,
                            __half* __restrict__ g16a, __half* __restrict__ g16b,
                            float* __restrict__ biasor,
                            const float* __restrict__ W1b, const float* __restrict__ W2b,
                            __half* __restrict__ W16)
{
    int bx = blockIdx.x;
    if (bx >= 384) { convert_chunk(bx - 384 + CV1 + CV2, W1b, W2b, W16); return; }

    const int BM = 64, BN = 64, BK = 16;
    bool isB = (bx >= 256);
    const float* B;
    const float* bias;
    __half* g16 = nullptr;
    int ldb, kz = 0, m0, n0;
    if (isB) {
        int r = bx - 256;
        n0 = (r & 15) * BN; m0 = (r >> 4) * BM;
        B = Wb; bias = bb; ldb = OUT_DIM;
    } else {
        int z = bx >> 5, r = bx & 31;
        kz = z & 3;
        n0 = (r & 3) * BN; m0 = (r >> 2) * BM;
        B = (z < 4 ? W1a : W2a) + (long)kz * C_DIM * C_DIM;
        bias = (z < 4 ? b1a : b2a) + kz * C_DIM;
        g16 = (z < 4 ? g16a : g16b);
        ldb = C_DIM;
    }

    __shared__ float As[BK][BM];
    __shared__ float Bs[BK][BN];
    int tid = threadIdx.x;
    int tx = tid % 16, ty = tid / 16;
    int arow = tid / 4, aq = tid % 4;
    int brow = tid / 16, bq = tid % 16;
    float acc[4][4] = {};

    for (int k0 = 0; k0 < C_DIM; k0 += BK) {
        float4 av = *(const float4*)&c[(m0 + arow) * C_DIM + k0 + aq * 4];
        As[aq * 4 + 0][arow] = av.x;
        As[aq * 4 + 1][arow] = av.y;
        As[aq * 4 + 2][arow] = av.z;
        As[aq * 4 + 3][arow] = av.w;
        *(float4*)&Bs[brow][bq * 4] =
            *(const float4*)&B[(k0 + brow) * ldb + n0 + bq * 4];
        __syncthreads();
#pragma unroll
        for (int k = 0; k < BK; k++) {
            float a[4], b[4];
#pragma unroll
            for (int i = 0; i < 4; i++) a[i] = As[k][ty * 4 + i];
#pragma unroll
            for (int j = 0; j < 4; j++) b[j] = Bs[k][tx * 4 + j];
#pragma unroll
            for (int i = 0; i < 4; i++)
#pragma unroll
                for (int j = 0; j < 4; j++) acc[i][j] += a[i] * b[j];
        }
        __syncthreads();
    }

#pragma unroll
    for (int i = 0; i < 4; i++) {
        int m = m0 + ty * 4 + i;
        float cf = isB ? 1.0f : coeffs[m * K_EXP + kz];
#pragma unroll
        for (int j = 0; j < 4; j++) {
            int n = n0 + tx * 4 + j;
            float v = acc[i][j] + bias[n];
            if (isB) {
                biasor[m * OUT_DIM + n] = v;
            } else {
                v = cf * silu_f(v);
                g16[m * KC + kz * C_DIM + n] = __float2half(v);
            }
        }
    }
}

// -------------------- big GEMM on mma.sync (fp16) --------------------------
// z = blockIdx.z picks (A16, W16 plane, bB, Mout plane). Merged launch.
// 3-stage cp.async ring + wait_group 1 (one load always in flight);
// 96 KB smem -> still 2 CTAs/SM.
#define STG_SZ 32768
#define B_OFF 16384
#define NSTG 3
#define BGEMM_SMEM (NSTG * STG_SZ)   // 96 KB

__global__ void __launch_bounds__(256, 2) bgemm_half(
    const __half* __restrict__ A16a, const __half* __restrict__ A16b,
    const __half* __restrict__ W16,
    __half* __restrict__ Mbuf,
    const float* __restrict__ bB1, const float* __restrict__ bB2,
    const float* __restrict__ coeffs)
{
    extern __shared__ __align__(128) char smem[];
    const uint32_t sbase = smem_u32(smem);
    const int tid = threadIdx.x, wid = tid >> 5, lane = tid & 31;
    const int m0 = blockIdx.x * 128, n0 = blockIdx.y * 128;
    const int z = blockIdx.z;
    const int warp_m = wid & 1, warp_n = wid >> 1;

    const __half* A16 = z ? A16b : A16a;
    const __half* W = W16 + (size_t)z * W_ELEMS;
    const float* bB = z ? bB2 : bB1;
    __half* Mout = Mbuf + (size_t)z * T_TOK * D_BIG;

    float acc[4][4][4] = {};

    const int a_m = tid >> 2;
    const int a_q = tid & 3;
    const int b_k = tid >> 2;
    const int b_cq = tid & 3;

    const int aRow = warp_m * 64 + (lane & 15);
    const uint32_t axor = ((uint32_t)(aRow & 7)) << 4;
    const uint32_t aKhalf = ((lane >> 4) & 1) * 16;
    uint32_t kOff[4];
#pragma unroll
    for (int ks = 0; ks < 4; ks++)
        kOff[ks] = ((uint32_t)(ks * 32) + aKhalf) ^ axor;
    const uint32_t aBase = (uint32_t)aRow * 128;

    const int kLoc = (lane & 7) | (((lane >> 3) & 1) << 3);
    const uint32_t bxor = ((uint32_t)(kLoc & 7)) << 4;
    const uint32_t bBase = (uint32_t)kLoc * 256;
    uint32_t nbp[2];
#pragma unroll
    for (int p = 0; p < 2; p++)
        nbp[p] = ((uint32_t)((warp_n * 32 + p * 16 + ((lane >> 4) & 1) * 8) * 2)) ^ bxor;

    auto issue = [&](int it, int buf) {
        uint32_t s = sbase + buf * STG_SZ;
        int k0 = it * 64;
#pragma unroll
        for (int i = 0; i < 4; i++) {
            int m = a_m + (i & 1) * 64;
            int q = a_q + (i >> 1) * 4;
            const __half* src = A16 + (size_t)(m0 + m) * KC + k0 + q * 8;
            uint32_t dst = s + (uint32_t)m * 128 +
                           (((uint32_t)(q * 16)) ^ (((uint32_t)(m & 7)) << 4));
            CP_ASYNC16(dst, src);
        }
#pragma unroll
        for (int i = 0; i < 4; i++) {
            int chunk = b_cq + i * 4;
            const __half* src = W + (size_t)(k0 + b_k) * D_BIG + n0 + chunk * 8;
            uint32_t dst = s + B_OFF + (uint32_t)b_k * 256 +
                           (((uint32_t)(chunk * 16)) ^ (((uint32_t)(b_k & 7)) << 4));
            CP_ASYNC16(dst, src);
        }
        CP_COMMIT();
    };
    auto mmaStage = [&](int buf) {
        uint32_t sA = sbase + buf * STG_SZ;
        uint32_t sB = sA + B_OFF;
#pragma unroll
        for (int ks = 0; ks < 4; ks++) {
            uint32_t ah[4][4], bb[2][4];
#pragma unroll
            for (int mt = 0; mt < 4; mt++)
                LDSM4(ah[mt], sA + aBase + mt * 2048 + kOff[ks]);
#pragma unroll
            for (int p = 0; p < 2; p++)
                LDSM4T(bb[p], sB + ks * 4096 + bBase + nbp[p]);
#pragma unroll
            for (int mt = 0; mt < 4; mt++)
#pragma unroll
                for (int nt = 0; nt < 4; nt++)
                    MMA_F16(acc[mt][nt], ah[mt],
                            bb[nt >> 1][(nt & 1) * 2], bb[nt >> 1][(nt & 1) * 2 + 1]);
        }
    };

    // prologue: 2 stages in flight
    issue(0, 0);
    issue(1, 1);

    // main loop: wait for the stage being consumed (<=1 pending keeps the
    // next load in flight); buffer (it+2)%3 was consumed in iter it-1, and
    // the sync after the wait orders that consumption before the overwrite.
    int buf = 0;
    for (int it = 0; it < 16; ++it) {
        if (it < 15) CP_WAIT1(); else CP_WAIT0();
        __syncthreads();
        if (it + 2 < 16) {
            int nb = buf + 2; if (nb >= 3) nb -= 3;
            issue(it + 2, nb);
        }
        mmaStage(buf);
        __syncthreads();
        if (++buf == 3) buf = 0;
    }

    // epilogue: mixed-expert bias, fp16 stores
    const int mw = m0 + warp_m * 64;
    const int nw = n0 + warp_n * 32;
    const int row = lane >> 2, colq = (lane & 3) * 2;
#pragma unroll
    for (int nt = 0; nt < 4; nt++) {
        int n = nw + nt * 8 + colq;
        float bv[K_EXP][2];
#pragma unroll
        for (int e = 0; e < K_EXP; e++) {
            bv[e][0] = bB[(size_t)e * D_BIG + n];
            bv[e][1] = bB[(size_t)e * D_BIG + n + 1];
        }
#pragma unroll
        for (int mt = 0; mt < 4; mt++) {
            int m = mw + mt * 16 + row;
            float4 c0 = *(const float4*)(coeffs + m * 4);
            float4 c1 = *(const float4*)(coeffs + (m + 8) * 4);
            float b00 = c0.x * bv[0][0] + c0.y * bv[1][0] + c0.z * bv[2][0] + c0.w * bv[3][0];
            float b01 = c0.x * bv[0][1] + c0.y * bv[1][1] + c0.z * bv[2][1] + c0.w * bv[3][1];
            float b10 = c1.x * bv[0][0] + c1.y * bv[1][0] + c1.z * bv[2][0] + c1.w * bv[3][0];
            float b11 = c1.x * bv[0][1] + c1.y * bv[1][1] + c1.z * bv[2][1] + c1.w * bv[3][1];
            __half2 h0 = __floats2half2_rn(acc[mt][nt][0] + b00, acc[mt][nt][1] + b01);
            __half2 h1 = __floats2half2_rn(acc[mt][nt][2] + b10, acc[mt][nt][3] + b11);
            *(__half2*)(Mout + (size_t)m * D_BIG + n) = h0;
            *(__half2*)(Mout + (size_t)(m + 8) * D_BIG + n) = h1;
        }
    }
}

// -------------------- Monarch stage: per-(token,g) 32x32 GEMV (fp16 M) -----
template<int STAGE>
__global__ void monarch_kernel(const float* __restrict__ X,
                               const __half* __restrict__ Mbuf,
                               float* __restrict__ out,
                               const float* __restrict__ ratio,
                               const float* __restrict__ biasor)
{
    __shared__ float xs[1024];
    int t = blockIdx.x;
    int tid = threadIdx.x;   // 256
#pragma unroll
    for (int i = tid; i < 1024; i += 256) xs[i] = X[t * 1024 + i];
    __syncthreads();

    int o = tid & 31, w = tid >> 5;
    const __half* Mrow = Mbuf + (size_t)t * D_BIG;
#pragma unroll
    for (int gi = 0; gi < 4; gi++) {
        int g = w * 4 + gi;
        float acc = 0.0f;
        const __half* mp = Mrow + g * 1024 + o;
#pragma unroll
        for (int i = 0; i < 32; i++) acc += xs[g * 32 + i] * __half2float(mp[i * 32]);
        if (STAGE == 1) {
            out[t * 1024 + o * 32 + g] = acc;           // transposed for stage 2
        } else {
            int idx = t * 1024 + g * 32 + o;
            out[idx] = acc * ratio[t] + biasor[idx];
        }
    }
}

// ---------------------------------------------------------------------------
extern "C" void kernel_launch(void* const* d_in, const int* in_sizes, int n_in,
                              void* d_out, int out_size)
{
    const float* x   = (const float*)d_in[0];
    const float* Wc  = (const float*)d_in[1];
    const float* bc  = (const float*)d_in[2];
    const float* W1a = (const float*)d_in[3];
    const float* b1a = (const float*)d_in[4];
    const float* W1b = (const float*)d_in[5];
    const float* b1b = (const float*)d_in[6];
    const float* W2a = (const float*)d_in[7];
    const float* b2a = (const float*)d_in[8];
    const float* W2b = (const float*)d_in[9];
    const float* b2b = (const float*)d_in[10];
    const float* Wm1 = (const float*)d_in[11];
    const float* bm1 = (const float*)d_in[12];
    const float* Wm2 = (const float*)d_in[13];
    const float* bm2 = (const float*)d_in[14];
    const float* Wb  = (const float*)d_in[15];
    const float* bb  = (const float*)d_in[16];
    const float* Wr  = (const float*)d_in[17];
    const float* br  = (const float*)d_in[18];
    float* out = (float*)d_out;

    float *p_c, *p_co, *p_ra, *p_bi, *p_x1;
    __half *p_a, *p_b, *p_M, *p_w16;
    cudaGetSymbolAddress((void**)&p_c,   g_c);
    cudaGetSymbolAddress((void**)&p_a,   g_A16a);
    cudaGetSymbolAddress((void**)&p_b,   g_A16b);
    cudaGetSymbolAddress((void**)&p_co,  g_coeffs);
    cudaGetSymbolAddress((void**)&p_ra,  g_ratio);
    cudaGetSymbolAddress((void**)&p_bi,  g_biasor);
    cudaGetSymbolAddress((void**)&p_x1,  g_x1oT);
    cudaGetSymbolAddress((void**)&p_M,   g_M);
    cudaGetSymbolAddress((void**)&p_w16, g_W16);

    static bool attr_done = false;
    if (!attr_done) {
        cudaFuncSetAttribute(bgemm_half,
                             cudaFuncAttributeMaxDynamicSharedMemorySize,
                             BGEMM_SMEM);
        attr_done = true;
    }

    // L1: c = silu(x @ Wc + bc)  +  convert chunk 1
    k1_c_conv<<<32 + CV1, 256>>>(x, Wc, p_c, bc, W1b, W2b, p_w16);

    // L2: coeffs/ratio  +  convert chunk 2
    k2_mix_conv<<<512 + CV2, 256>>>(p_c, Wm1, bm1, Wm2, bm2, Wr, br,
                                    p_co, p_ra, W1b, W2b, p_w16);

    // L3: expert-gens (both stages) + biasor  +  convert chunk 3
    k3_gen_conv<<<384 + CV3, 256>>>(p_c, W1a, b1a, W2a, b2a, Wb, bb, p_co,
                                    p_a, p_b, p_bi, W1b, W2b, p_w16);

    // merged bgemm (z picks stage), 3-stage ring, 2 CTAs/SM
    bgemm_half<<<dim3(T_TOK / 128, D_BIG / 128, 2), 256, BGEMM_SMEM>>>(
        p_a, p_b, p_w16, p_M, b1b, b2b, p_co);

    // Monarch stage 1 (writes transposed)
    monarch_kernel<1><<<T_TOK, 256>>>(x, p_M, p_x1, nullptr, nullptr);

    // Monarch stage 2 + final epilogue
    monarch_kernel<2><<<T_TOK, 256>>>(
        p_x1, p_M + (size_t)T_TOK * D_BIG, out, p_ra, p_bi);
}

// round 15
// speedup vs baseline: 1.5653x; 1.0335x over previous
#include <cuda_runtime.h>
#include <cuda_bf16.h>
#include <cuda_fp16.h>
#include <cstdint>
#include <cstddef>

// ---------------------------------------------------------------------------
// HyperMoMixLinear on GB300 (sm_103a harness, PLAIN sm_103 ptx target).
// R15: barrier-count reduction. bgemm: 3-stage ring, ONE __syncthreads/iter
// (trailing sync proved redundant by program-order argument). Small GEMMs
// (k1 compressor, k3 gen/biasor): BK 16 -> 32, halving barrier crossings,
// same k-order => bitwise-identical fp32. Fat-kernel convert overlap kept.
// ---------------------------------------------------------------------------

#define T_TOK 512
#define C_DIM 256
#define IN_DIM 1024
#define OUT_DIM 1024
#define K_EXP 4
#define D_BIG 32768
#define KC 1024   // K_EXP * C_DIM  == GEMM K
#define W_ELEMS ((size_t)KC * D_BIG)

// convert work: 16384 chunks per weight, 32768 total; split across 3 launches
#define CV1 12288
#define CV2 4096
#define CV3 16384   // CV1+CV2+CV3 == 32768

// -------------------- device scratch (no runtime allocation) ---------------
__device__ float g_c[T_TOK * C_DIM];
__device__ __half g_A16a[T_TOK * KC];
__device__ __half g_A16b[T_TOK * KC];
__device__ float g_coeffs[T_TOK * K_EXP];
__device__ float g_ratio[T_TOK];
__device__ float g_biasor[T_TOK * OUT_DIM];
__device__ float g_x1oT[T_TOK * OUT_DIM];          // stage-1 out, transposed
__device__ __half g_M[2 * (size_t)T_TOK * D_BIG];  // 2 x 32 MB (M1, M2)
__device__ __half g_W16[2 * W_ELEMS];              // 128 MB fp16 weights

__device__ __forceinline__ float silu_f(float v) {
    return v / (1.0f + __expf(-v));
}

__device__ __forceinline__ uint32_t smem_u32(const void* p) {
    uint32_t a;
    asm("{ .reg .u64 t; cvta.to.shared.u64 t, %1; cvt.u32.u64 %0, t; }"
        : "=r"(a) : "l"(p));
    return a;
}

#define CP_ASYNC16(dst, src) \
    asm volatile("cp.async.cg.shared.global [%0], [%1], 16;" \
                 :: "r"(dst), "l"(src) : "memory")
#define CP_COMMIT() asm volatile("cp.async.commit_group;" ::: "memory")
#define CP_WAIT0()  asm volatile("cp.async.wait_group 0;" ::: "memory")
#define CP_WAIT1()  asm volatile("cp.async.wait_group 1;" ::: "memory")

#define LDSM4(r, addr) \
    asm volatile("ldmatrix.sync.aligned.m8n8.x4.shared.b16 {%0,%1,%2,%3}, [%4];" \
        : "=r"((r)[0]), "=r"((r)[1]), "=r"((r)[2]), "=r"((r)[3]) : "r"(addr))
#define LDSM4T(r, addr) \
    asm volatile("ldmatrix.sync.aligned.m8n8.x4.trans.shared.b16 {%0,%1,%2,%3}, [%4];" \
        : "=r"((r)[0]), "=r"((r)[1]), "=r"((r)[2]), "=r"((r)[3]) : "r"(addr))

#define MMA_F16(d, a, b0v, b1v) \
    asm volatile("mma.sync.aligned.m16n8k16.row.col.f32.f16.f16.f32 " \
        "{%0,%1,%2,%3}, {%4,%5,%6,%7}, {%8,%9}, {%0,%1,%2,%3};" \
        : "+f"((d)[0]), "+f"((d)[1]), "+f"((d)[2]), "+f"((d)[3]) \
        : "r"((a)[0]), "r"((a)[1]), "r"((a)[2]), "r"((a)[3]), \
          "r"(b0v), "r"(b1v))

// -------------------- convert chunk (one block's share) --------------------
__device__ __forceinline__ void convert_chunk(int cb,
                                              const float* __restrict__ W1b,
                                              const float* __restrict__ W2b,
                                              __half* __restrict__ W16)
{
    const float* W = (cb >= 16384) ? W2b : W1b;
    __half* dst = W16 + ((cb >= 16384) ? W_ELEMS : 0);
    int b = cb & 16383;
    size_t base = ((size_t)b * 256 + threadIdx.x) * 8;
    float4 v0 = *(const float4*)(W + base);
    float4 v1 = *(const float4*)(W + base + 4);
    __half2 h0 = __floats2half2_rn(v0.x, v0.y);
    __half2 h1 = __floats2half2_rn(v0.z, v0.w);
    __half2 h2 = __floats2half2_rn(v1.x, v1.y);
    __half2 h3 = __floats2half2_rn(v1.z, v1.w);
    uint4 o;
    o.x = *(uint32_t*)&h0; o.y = *(uint32_t*)&h1;
    o.z = *(uint32_t*)&h2; o.w = *(uint32_t*)&h3;
    *(uint4*)(dst + base) = o;
}

// -------------------- shared BK=32 64x64 fp32 GEMM body --------------------
// As/Bs provided by caller; computes acc over K=Kd from A (lda) and B (ldb).
// Summation order over k identical to BK=16 version -> bitwise-same results.
template<int KD>
__device__ __forceinline__ void gemm64_bk32(
    const float* __restrict__ A, int lda, int m0,
    const float* __restrict__ B, int ldb, int n0,
    float (&acc)[4][4], float (*As)[64], float (*Bs)[64])
{
    int tid = threadIdx.x;
    int tx = tid % 16, ty = tid / 16;
    int arow = tid >> 2, aq = tid & 3;     // A: 64 rows, 2 x float4 per thread
    int brow = tid >> 3, bq = tid & 7;     // B: 32 k-rows, 2 x float4 per thread

    for (int k0 = 0; k0 < KD; k0 += 32) {
#pragma unroll
        for (int h = 0; h < 2; h++) {
            int qc = aq + h * 4;           // float4 index within 32 cols
            float4 av = *(const float4*)&A[(m0 + arow) * lda + k0 + qc * 4];
            As[qc * 4 + 0][arow] = av.x;
            As[qc * 4 + 1][arow] = av.y;
            As[qc * 4 + 2][arow] = av.z;
            As[qc * 4 + 3][arow] = av.w;
        }
#pragma unroll
        for (int h = 0; h < 2; h++) {
            int qc = bq + h * 8;
            *(float4*)&Bs[brow][qc * 4] =
                *(const float4*)&B[(k0 + brow) * ldb + n0 + qc * 4];
        }
        __syncthreads();
#pragma unroll
        for (int k = 0; k < 32; k++) {
            float a[4], b[4];
#pragma unroll
            for (int i = 0; i < 4; i++) a[i] = As[k][ty * 4 + i];
#pragma unroll
            for (int j = 0; j < 4; j++) b[j] = Bs[k][tx * 4 + j];
#pragma unroll
            for (int i = 0; i < 4; i++)
#pragma unroll
                for (int j = 0; j < 4; j++) acc[i][j] += a[i] * b[j];
        }
        __syncthreads();
    }
}

// -------------------- L1: compressor GEMM + convert chunk ------------------
__global__ void k1_c_conv(const float* __restrict__ x, const float* __restrict__ Wc,
                          float* __restrict__ c, const float* __restrict__ bc,
                          const float* __restrict__ W1b, const float* __restrict__ W2b,
                          __half* __restrict__ W16)
{
    int bx = blockIdx.x;
    if (bx >= 32) { convert_chunk(bx - 32, W1b, W2b, W16); return; }

    __shared__ float As[32][64];
    __shared__ float Bs[32][64];
    int m0 = (bx >> 2) * 64;
    int n0 = (bx & 3) * 64;
    float acc[4][4] = {};
    gemm64_bk32<IN_DIM>(x, IN_DIM, m0, Wc, C_DIM, n0, acc, As, Bs);

    int tid = threadIdx.x;
    int tx = tid % 16, ty = tid / 16;
#pragma unroll
    for (int i = 0; i < 4; i++) {
        int m = m0 + ty * 4 + i;
#pragma unroll
        for (int j = 0; j < 4; j++) {
            int n = n0 + tx * 4 + j;
            c[m * C_DIM + n] = silu_f(acc[i][j] + bc[n]);
        }
    }
}

// -------------------- L2: mixer + convert chunk ----------------------------
__global__ void k2_mix_conv(const float* __restrict__ c,
                            const float* __restrict__ Wm1, const float* __restrict__ bm1,
                            const float* __restrict__ Wm2, const float* __restrict__ bm2,
                            const float* __restrict__ Wr,  const float* __restrict__ br,
                            float* __restrict__ coeffs, float* __restrict__ ratio,
                            const float* __restrict__ W1b, const float* __restrict__ W2b,
                            __half* __restrict__ W16)
{
    int bx = blockIdx.x;
    if (bx >= 512) { convert_chunk(bx - 512 + CV1, W1b, W2b, W16); return; }

    __shared__ float cs[C_DIM];
    __shared__ float ms[C_DIM];
    __shared__ float red[C_DIM];
    __shared__ float lg[K_EXP];
    int t = bx, tid = threadIdx.x;

    cs[tid] = c[t * C_DIM + tid];
    __syncthreads();

    float acc = bm1[tid];
#pragma unroll 8
    for (int i = 0; i < C_DIM; i++) acc += cs[i] * Wm1[i * C_DIM + tid];
    ms[tid] = silu_f(acc);
    red[tid] = cs[tid] * Wr[tid];
    __syncthreads();

    if (tid < K_EXP) {
        float l = bm2[tid];
#pragma unroll 8
        for (int i = 0; i < C_DIM; i++) l += ms[i] * Wm2[i * K_EXP + tid];
        lg[tid] = l;
    }
    for (int s = 128; s > 0; s >>= 1) {
        __syncthreads();
        if (tid < s) red[tid] += red[tid + s];
    }
    __syncthreads();

    if (tid == 0) {
        ratio[t] = red[0] + br[0];
        float mx = fmaxf(fmaxf(lg[0], lg[1]), fmaxf(lg[2], lg[3]));
        float e0 = __expf(lg[0] - mx), e1 = __expf(lg[1] - mx);
        float e2 = __expf(lg[2] - mx), e3 = __expf(lg[3] - mx);
        float inv = 1.0f / (e0 + e1 + e2 + e3);
        coeffs[t * 4 + 0] = e0 * inv;
        coeffs[t * 4 + 1] = e1 * inv;
        coeffs[t * 4 + 2] = e2 * inv;
        coeffs[t * 4 + 3] = e3 * inv;
    }
}

// -------------------- L3: expert-gens + biasor + convert chunk -------------
__global__ void k3_gen_conv(const float* __restrict__ c,
                            const float* __restrict__ W1a, const float* __restrict__ b1a,
                            const float* __restrict__ W2a, const float* __restrict__ b2a,
                            const float* __restrict__ Wb,  const float* __restrict__ bb,
                            const float* __restrict__ coeffs,
                            __half* __restrict__ g16a, __half* __restrict__ g16b,
                            float* __restrict__ biasor,
                            const float* __restrict__ W1b, const float* __restrict__ W2b,
                            __half* __restrict__ W16)
{
    int bx = blockIdx.x;
    if (bx >= 384) { convert_chunk(bx - 384 + CV1 + CV2, W1b, W2b, W16); return; }

    bool isB = (bx >= 256);
    const float* B;
    const float* bias;
    __half* g16 = nullptr;
    int ldb, kz = 0, m0, n0;
    if (isB) {
        int r = bx - 256;
        n0 = (r & 15) * 64; m0 = (r >> 4) * 64;
        B = Wb; bias = bb; ldb = OUT_DIM;
    } else {
        int z = bx >> 5, r = bx & 31;
        kz = z & 3;
        n0 = (r & 3) * 64; m0 = (r >> 2) * 64;
        B = (z < 4 ? W1a : W2a) + (long)kz * C_DIM * C_DIM;
        bias = (z < 4 ? b1a : b2a) + kz * C_DIM;
        g16 = (z < 4 ? g16a : g16b);
        ldb = C_DIM;
    }

    __shared__ float As[32][64];
    __shared__ float Bs[32][64];
    float acc[4][4] = {};
    gemm64_bk32<C_DIM>(c, C_DIM, m0, B, ldb, n0, acc, As, Bs);

    int tid = threadIdx.x;
    int tx = tid % 16, ty = tid / 16;
#pragma unroll
    for (int i = 0; i < 4; i++) {
        int m = m0 + ty * 4 + i;
        float cf = isB ? 1.0f : coeffs[m * K_EXP + kz];
#pragma unroll
        for (int j = 0; j < 4; j++) {
            int n = n0 + tx * 4 + j;
            float v = acc[i][j] + bias[n];
            if (isB) {
                biasor[m * OUT_DIM + n] = v;
            } else {
                v = cf * silu_f(v);
                g16[m * KC + kz * C_DIM + n] = __float2half(v);
            }
        }
    }
}

// -------------------- big GEMM on mma.sync (fp16) --------------------------
// 3-stage cp.async ring + wait_group 1; ONE __syncthreads per iteration.
// 96 KB smem -> 2 CTAs/SM.
#define STG_SZ 32768
#define B_OFF 16384
#define NSTG 3
#define BGEMM_SMEM (NSTG * STG_SZ)   // 96 KB

__global__ void __launch_bounds__(256, 2) bgemm_half(
    const __half* __restrict__ A16a, const __half* __restrict__ A16b,
    const __half* __restrict__ W16,
    __half* __restrict__ Mbuf,
    const float* __restrict__ bB1, const float* __restrict__ bB2,
    const float* __restrict__ coeffs)
{
    extern __shared__ __align__(128) char smem[];
    const uint32_t sbase = smem_u32(smem);
    const int tid = threadIdx.x, wid = tid >> 5, lane = tid & 31;
    const int m0 = blockIdx.x * 128, n0 = blockIdx.y * 128;
    const int z = blockIdx.z;
    const int warp_m = wid & 1, warp_n = wid >> 1;

    const __half* A16 = z ? A16b : A16a;
    const __half* W = W16 + (size_t)z * W_ELEMS;
    const float* bB = z ? bB2 : bB1;
    __half* Mout = Mbuf + (size_t)z * T_TOK * D_BIG;

    float acc[4][4][4] = {};

    const int a_m = tid >> 2;
    const int a_q = tid & 3;
    const int b_k = tid >> 2;
    const int b_cq = tid & 3;

    const int aRow = warp_m * 64 + (lane & 15);
    const uint32_t axor = ((uint32_t)(aRow & 7)) << 4;
    const uint32_t aKhalf = ((lane >> 4) & 1) * 16;
    uint32_t kOff[4];
#pragma unroll
    for (int ks = 0; ks < 4; ks++)
        kOff[ks] = ((uint32_t)(ks * 32) + aKhalf) ^ axor;
    const uint32_t aBase = (uint32_t)aRow * 128;

    const int kLoc = (lane & 7) | (((lane >> 3) & 1) << 3);
    const uint32_t bxor = ((uint32_t)(kLoc & 7)) << 4;
    const uint32_t bBase = (uint32_t)kLoc * 256;
    uint32_t nbp[2];
#pragma unroll
    for (int p = 0; p < 2; p++)
        nbp[p] = ((uint32_t)((warp_n * 32 + p * 16 + ((lane >> 4) & 1) * 8) * 2)) ^ bxor;

    auto issue = [&](int it, int buf) {
        uint32_t s = sbase + buf * STG_SZ;
        int k0 = it * 64;
#pragma unroll
        for (int i = 0; i < 4; i++) {
            int m = a_m + (i & 1) * 64;
            int q = a_q + (i >> 1) * 4;
            const __half* src = A16 + (size_t)(m0 + m) * KC + k0 + q * 8;
            uint32_t dst = s + (uint32_t)m * 128 +
                           (((uint32_t)(q * 16)) ^ (((uint32_t)(m & 7)) << 4));
            CP_ASYNC16(dst, src);
        }
#pragma unroll
        for (int i = 0; i < 4; i++) {
            int chunk = b_cq + i * 4;
            const __half* src = W + (size_t)(k0 + b_k) * D_BIG + n0 + chunk * 8;
            uint32_t dst = s + B_OFF + (uint32_t)b_k * 256 +
                           (((uint32_t)(chunk * 16)) ^ (((uint32_t)(b_k & 7)) << 4));
            CP_ASYNC16(dst, src);
        }
        CP_COMMIT();
    };
    auto mmaStage = [&](int buf) {
        uint32_t sA = sbase + buf * STG_SZ;
        uint32_t sB = sA + B_OFF;
#pragma unroll
        for (int ks = 0; ks < 4; ks++) {
            uint32_t ah[4][4], bb[2][4];
#pragma unroll
            for (int mt = 0; mt < 4; mt++)
                LDSM4(ah[mt], sA + aBase + mt * 2048 + kOff[ks]);
#pragma unroll
            for (int p = 0; p < 2; p++)
                LDSM4T(bb[p], sB + ks * 4096 + bBase + nbp[p]);
#pragma unroll
            for (int mt = 0; mt < 4; mt++)
#pragma unroll
                for (int nt = 0; nt < 4; nt++)
                    MMA_F16(acc[mt][nt], ah[mt],
                            bb[nt >> 1][(nt & 1) * 2], bb[nt >> 1][(nt & 1) * 2 + 1]);
        }
    };

    // prologue: 2 stages in flight
    issue(0, 0);
    issue(1, 1);

    // main loop: ONE barrier per iter. The top sync (after the wait) orders
    // every warp's iter-(it-1) mmaStage before this iter's issue into
    // (it+2)%3 (that buffer was consumed in iter it-1), and also publishes
    // the completed cp.async data for this iter's mmaStage.
    int buf = 0;
    for (int it = 0; it < 16; ++it) {
        if (it < 15) CP_WAIT1(); else CP_WAIT0();
        __syncthreads();
        if (it + 2 < 16) {
            int nb = buf + 2; if (nb >= 3) nb -= 3;
            issue(it + 2, nb);
        }
        mmaStage(buf);
        if (++buf == 3) buf = 0;
    }

    // epilogue: mixed-expert bias, fp16 stores
    const int mw = m0 + warp_m * 64;
    const int nw = n0 + warp_n * 32;
    const int row = lane >> 2, colq = (lane & 3) * 2;
#pragma unroll
    for (int nt = 0; nt < 4; nt++) {
        int n = nw + nt * 8 + colq;
        float bv[K_EXP][2];
#pragma unroll
        for (int e = 0; e < K_EXP; e++) {
            bv[e][0] = bB[(size_t)e * D_BIG + n];
            bv[e][1] = bB[(size_t)e * D_BIG + n + 1];
        }
#pragma unroll
        for (int mt = 0; mt < 4; mt++) {
            int m = mw + mt * 16 + row;
            float4 c0 = *(const float4*)(coeffs + m * 4);
            float4 c1 = *(const float4*)(coeffs + (m + 8) * 4);
            float b00 = c0.x * bv[0][0] + c0.y * bv[1][0] + c0.z * bv[2][0] + c0.w * bv[3][0];
            float b01 = c0.x * bv[0][1] + c0.y * bv[1][1] + c0.z * bv[2][1] + c0.w * bv[3][1];
            float b10 = c1.x * bv[0][0] + c1.y * bv[1][0] + c1.z * bv[2][0] + c1.w * bv[3][0];
            float b11 = c1.x * bv[0][1] + c1.y * bv[1][1] + c1.z * bv[2][1] + c1.w * bv[3][1];
            __half2 h0 = __floats2half2_rn(acc[mt][nt][0] + b00, acc[mt][nt][1] + b01);
            __half2 h1 = __floats2half2_rn(acc[mt][nt][2] + b10, acc[mt][nt][3] + b11);
            *(__half2*)(Mout + (size_t)m * D_BIG + n) = h0;
            *(__half2*)(Mout + (size_t)(m + 8) * D_BIG + n) = h1;
        }
    }
}

// -------------------- Monarch stage: per-(token,g) 32x32 GEMV (fp16 M) -----
template<int STAGE>
__global__ void monarch_kernel(const float* __restrict__ X,
                               const __half* __restrict__ Mbuf,
                               float* __restrict__ out,
                               const float* __restrict__ ratio,
                               const float* __restrict__ biasor)
{
    __shared__ float xs[1024];
    int t = blockIdx.x;
    int tid = threadIdx.x;   // 256
#pragma unroll
    for (int i = tid; i < 1024; i += 256) xs[i] = X[t * 1024 + i];
    __syncthreads();

    int o = tid & 31, w = tid >> 5;
    const __half* Mrow = Mbuf + (size_t)t * D_BIG;
#pragma unroll
    for (int gi = 0; gi < 4; gi++) {
        int g = w * 4 + gi;
        float acc = 0.0f;
        const __half* mp = Mrow + g * 1024 + o;
#pragma unroll
        for (int i = 0; i < 32; i++) acc += xs[g * 32 + i] * __half2float(mp[i * 32]);
        if (STAGE == 1) {
            out[t * 1024 + o * 32 + g] = acc;           // transposed for stage 2
        } else {
            int idx = t * 1024 + g * 32 + o;
            out[idx] = acc * ratio[t] + biasor[idx];
        }
    }
}

// ---------------------------------------------------------------------------
extern "C" void kernel_launch(void* const* d_in, const int* in_sizes, int n_in,
                              void* d_out, int out_size)
{
    const float* x   = (const float*)d_in[0];
    const float* Wc  = (const float*)d_in[1];
    const float* bc  = (const float*)d_in[2];
    const float* W1a = (const float*)d_in[3];
    const float* b1a = (const float*)d_in[4];
    const float* W1b = (const float*)d_in[5];
    const float* b1b = (const float*)d_in[6];
    const float* W2a = (const float*)d_in[7];
    const float* b2a = (const float*)d_in[8];
    const float* W2b = (const float*)d_in[9];
    const float* b2b = (const float*)d_in[10];
    const float* Wm1 = (const float*)d_in[11];
    const float* bm1 = (const float*)d_in[12];
    const float* Wm2 = (const float*)d_in[13];
    const float* bm2 = (const float*)d_in[14];
    const float* Wb  = (const float*)d_in[15];
    const float* bb  = (const float*)d_in[16];
    const float* Wr  = (const float*)d_in[17];
    const float* br  = (const float*)d_in[18];
    float* out = (float*)d_out;

    float *p_c, *p_co, *p_ra, *p_bi, *p_x1;
    __half *p_a, *p_b, *p_M, *p_w16;
    cudaGetSymbolAddress((void**)&p_c,   g_c);
    cudaGetSymbolAddress((void**)&p_a,   g_A16a);
    cudaGetSymbolAddress((void**)&p_b,   g_A16b);
    cudaGetSymbolAddress((void**)&p_co,  g_coeffs);
    cudaGetSymbolAddress((void**)&p_ra,  g_ratio);
    cudaGetSymbolAddress((void**)&p_bi,  g_biasor);
    cudaGetSymbolAddress((void**)&p_x1,  g_x1oT);
    cudaGetSymbolAddress((void**)&p_M,   g_M);
    cudaGetSymbolAddress((void**)&p_w16, g_W16);

    static bool attr_done = false;
    if (!attr_done) {
        cudaFuncSetAttribute(bgemm_half,
                             cudaFuncAttributeMaxDynamicSharedMemorySize,
                             BGEMM_SMEM);
        attr_done = true;
    }

    // L1: c = silu(x @ Wc + bc)  +  convert chunk 1
    k1_c_conv<<<32 + CV1, 256>>>(x, Wc, p_c, bc, W1b, W2b, p_w16);

    // L2: coeffs/ratio  +  convert chunk 2
    k2_mix_conv<<<512 + CV2, 256>>>(p_c, Wm1, bm1, Wm2, bm2, Wr, br,
                                    p_co, p_ra, W1b, W2b, p_w16);

    // L3: expert-gens (both stages) + biasor  +  convert chunk 3
    k3_gen_conv<<<384 + CV3, 256>>>(p_c, W1a, b1a, W2a, b2a, Wb, bb, p_co,
                                    p_a, p_b, p_bi, W1b, W2b, p_w16);

    // merged bgemm (z picks stage), 3-stage ring, 2 CTAs/SM
    bgemm_half<<<dim3(T_TOK / 128, D_BIG / 128, 2), 256, BGEMM_SMEM>>>(
        p_a, p_b, p_w16, p_M, b1b, b2b, p_co);

    // Monarch stage 1 (writes transposed)
    monarch_kernel<1><<<T_TOK, 256>>>(x, p_M, p_x1, nullptr, nullptr);

    // Monarch stage 2 + final epilogue
    monarch_kernel<2><<<T_TOK, 256>>>(
        p_x1, p_M + (size_t)T_TOK * D_BIG, out, p_ra, p_bi);
}

// round 16
// speedup vs baseline: 1.6573x; 1.0588x over previous
#include <cuda_runtime.h>
#include <cuda_bf16.h>
#include <cuda_fp16.h>
#include <cstdint>
#include <cstddef>

// ---------------------------------------------------------------------------
// HyperMoMixLinear on GB300 (sm_103a harness, PLAIN sm_103 ptx target).
// R16: bgemm smem-traffic cut. ncu showed tensor pinned ~59% with L1=57%:
// the smem crossbar (LDSM) co-saturates with the HMMA pipe. Widen warp tile
// to 64x64 (4 warps/CTA, 128 thr), cutting LDSM bytes/MMA 192->128 and
// CTA-iter smem 128KB->96KB. Same k-order => bitwise-identical results.
// Everything else identical to R15.
// ---------------------------------------------------------------------------

#define T_TOK 512
#define C_DIM 256
#define IN_DIM 1024
#define OUT_DIM 1024
#define K_EXP 4
#define D_BIG 32768
#define KC 1024   // K_EXP * C_DIM  == GEMM K
#define W_ELEMS ((size_t)KC * D_BIG)

// convert work: 16384 chunks per weight, 32768 total; split across 3 launches
#define CV1 12288
#define CV2 4096
#define CV3 16384   // CV1+CV2+CV3 == 32768

// -------------------- device scratch (no runtime allocation) ---------------
__device__ float g_c[T_TOK * C_DIM];
__device__ __half g_A16a[T_TOK * KC];
__device__ __half g_A16b[T_TOK * KC];
__device__ float g_coeffs[T_TOK * K_EXP];
__device__ float g_ratio[T_TOK];
__device__ float g_biasor[T_TOK * OUT_DIM];
__device__ float g_x1oT[T_TOK * OUT_DIM];          // stage-1 out, transposed
__device__ __half g_M[2 * (size_t)T_TOK * D_BIG];  // 2 x 32 MB (M1, M2)
__device__ __half g_W16[2 * W_ELEMS];              // 128 MB fp16 weights

__device__ __forceinline__ float silu_f(float v) {
    return v / (1.0f + __expf(-v));
}

__device__ __forceinline__ uint32_t smem_u32(const void* p) {
    uint32_t a;
    asm("{ .reg .u64 t; cvta.to.shared.u64 t, %1; cvt.u32.u64 %0, t; }"
        : "=r"(a) : "l"(p));
    return a;
}

#define CP_ASYNC16(dst, src) \
    asm volatile("cp.async.cg.shared.global [%0], [%1], 16;" \
                 :: "r"(dst), "l"(src) : "memory")
#define CP_COMMIT() asm volatile("cp.async.commit_group;" ::: "memory")
#define CP_WAIT0()  asm volatile("cp.async.wait_group 0;" ::: "memory")
#define CP_WAIT1()  asm volatile("cp.async.wait_group 1;" ::: "memory")

#define LDSM4(r, addr) \
    asm volatile("ldmatrix.sync.aligned.m8n8.x4.shared.b16 {%0,%1,%2,%3}, [%4];" \
        : "=r"((r)[0]), "=r"((r)[1]), "=r"((r)[2]), "=r"((r)[3]) : "r"(addr))
#define LDSM4T(r, addr) \
    asm volatile("ldmatrix.sync.aligned.m8n8.x4.trans.shared.b16 {%0,%1,%2,%3}, [%4];" \
        : "=r"((r)[0]), "=r"((r)[1]), "=r"((r)[2]), "=r"((r)[3]) : "r"(addr))

#define MMA_F16(d, a, b0v, b1v) \
    asm volatile("mma.sync.aligned.m16n8k16.row.col.f32.f16.f16.f32 " \
        "{%0,%1,%2,%3}, {%4,%5,%6,%7}, {%8,%9}, {%0,%1,%2,%3};" \
        : "+f"((d)[0]), "+f"((d)[1]), "+f"((d)[2]), "+f"((d)[3]) \
        : "r"((a)[0]), "r"((a)[1]), "r"((a)[2]), "r"((a)[3]), \
          "r"(b0v), "r"(b1v))

// -------------------- convert chunk (one block's share) --------------------
__device__ __forceinline__ void convert_chunk(int cb,
                                              const float* __restrict__ W1b,
                                              const float* __restrict__ W2b,
                                              __half* __restrict__ W16)
{
    const float* W = (cb >= 16384) ? W2b : W1b;
    __half* dst = W16 + ((cb >= 16384) ? W_ELEMS : 0);
    int b = cb & 16383;
    size_t base = ((size_t)b * 256 + threadIdx.x) * 8;
    float4 v0 = *(const float4*)(W + base);
    float4 v1 = *(const float4*)(W + base + 4);
    __half2 h0 = __floats2half2_rn(v0.x, v0.y);
    __half2 h1 = __floats2half2_rn(v0.z, v0.w);
    __half2 h2 = __floats2half2_rn(v1.x, v1.y);
    __half2 h3 = __floats2half2_rn(v1.z, v1.w);
    uint4 o;
    o.x = *(uint32_t*)&h0; o.y = *(uint32_t*)&h1;
    o.z = *(uint32_t*)&h2; o.w = *(uint32_t*)&h3;
    *(uint4*)(dst + base) = o;
}

// -------------------- shared BK=32 64x64 fp32 GEMM body --------------------
template<int KD>
__device__ __forceinline__ void gemm64_bk32(
    const float* __restrict__ A, int lda, int m0,
    const float* __restrict__ B, int ldb, int n0,
    float (&acc)[4][4], float (*As)[64], float (*Bs)[64])
{
    int tid = threadIdx.x;
    int tx = tid % 16, ty = tid / 16;
    int arow = tid >> 2, aq = tid & 3;
    int brow = tid >> 3, bq = tid & 7;

    for (int k0 = 0; k0 < KD; k0 += 32) {
#pragma unroll
        for (int h = 0; h < 2; h++) {
            int qc = aq + h * 4;
            float4 av = *(const float4*)&A[(m0 + arow) * lda + k0 + qc * 4];
            As[qc * 4 + 0][arow] = av.x;
            As[qc * 4 + 1][arow] = av.y;
            As[qc * 4 + 2][arow] = av.z;
            As[qc * 4 + 3][arow] = av.w;
        }
#pragma unroll
        for (int h = 0; h < 2; h++) {
            int qc = bq + h * 8;
            *(float4*)&Bs[brow][qc * 4] =
                *(const float4*)&B[(k0 + brow) * ldb + n0 + qc * 4];
        }
        __syncthreads();
#pragma unroll
        for (int k = 0; k < 32; k++) {
            float a[4], b[4];
#pragma unroll
            for (int i = 0; i < 4; i++) a[i] = As[k][ty * 4 + i];
#pragma unroll
            for (int j = 0; j < 4; j++) b[j] = Bs[k][tx * 4 + j];
#pragma unroll
            for (int i = 0; i < 4; i++)
#pragma unroll
                for (int j = 0; j < 4; j++) acc[i][j] += a[i] * b[j];
        }
        __syncthreads();
    }
}

// -------------------- L1: compressor GEMM + convert chunk ------------------
__global__ void k1_c_conv(const float* __restrict__ x, const float* __restrict__ Wc,
                          float* __restrict__ c, const float* __restrict__ bc,
                          const float* __restrict__ W1b, const float* __restrict__ W2b,
                          __half* __restrict__ W16)
{
    int bx = blockIdx.x;
    if (bx >= 32) { convert_chunk(bx - 32, W1b, W2b, W16); return; }

    __shared__ float As[32][64];
    __shared__ float Bs[32][64];
    int m0 = (bx >> 2) * 64;
    int n0 = (bx & 3) * 64;
    float acc[4][4] = {};
    gemm64_bk32<IN_DIM>(x, IN_DIM, m0, Wc, C_DIM, n0, acc, As, Bs);

    int tid = threadIdx.x;
    int tx = tid % 16, ty = tid / 16;
#pragma unroll
    for (int i = 0; i < 4; i++) {
        int m = m0 + ty * 4 + i;
#pragma unroll
        for (int j = 0; j < 4; j++) {
            int n = n0 + tx * 4 + j;
            c[m * C_DIM + n] = silu_f(acc[i][j] + bc[n]);
        }
    }
}

// -------------------- L2: mixer + convert chunk ----------------------------
__global__ void k2_mix_conv(const float* __restrict__ c,
                            const float* __restrict__ Wm1, const float* __restrict__ bm1,
                            const float* __restrict__ Wm2, const float* __restrict__ bm2,
                            const float* __restrict__ Wr,  const float* __restrict__ br,
                            float* __restrict__ coeffs, float* __restrict__ ratio,
                            const float* __restrict__ W1b, const float* __restrict__ W2b,
                            __half* __restrict__ W16)
{
    int bx = blockIdx.x;
    if (bx >= 512) { convert_chunk(bx - 512 + CV1, W1b, W2b, W16); return; }

    __shared__ float cs[C_DIM];
    __shared__ float ms[C_DIM];
    __shared__ float red[C_DIM];
    __shared__ float lg[K_EXP];
    int t = bx, tid = threadIdx.x;

    cs[tid] = c[t * C_DIM + tid];
    __syncthreads();

    float acc = bm1[tid];
#pragma unroll 8
    for (int i = 0; i < C_DIM; i++) acc += cs[i] * Wm1[i * C_DIM + tid];
    ms[tid] = silu_f(acc);
    red[tid] = cs[tid] * Wr[tid];
    __syncthreads();

    if (tid < K_EXP) {
        float l = bm2[tid];
#pragma unroll 8
        for (int i = 0; i < C_DIM; i++) l += ms[i] * Wm2[i * K_EXP + tid];
        lg[tid] = l;
    }
    for (int s = 128; s > 0; s >>= 1) {
        __syncthreads();
        if (tid < s) red[tid] += red[tid + s];
    }
    __syncthreads();

    if (tid == 0) {
        ratio[t] = red[0] + br[0];
        float mx = fmaxf(fmaxf(lg[0], lg[1]), fmaxf(lg[2], lg[3]));
        float e0 = __expf(lg[0] - mx), e1 = __expf(lg[1] - mx);
        float e2 = __expf(lg[2] - mx), e3 = __expf(lg[3] - mx);
        float inv = 1.0f / (e0 + e1 + e2 + e3);
        coeffs[t * 4 + 0] = e0 * inv;
        coeffs[t * 4 + 1] = e1 * inv;
        coeffs[t * 4 + 2] = e2 * inv;
        coeffs[t * 4 + 3] = e3 * inv;
    }
}

// -------------------- L3: expert-gens + biasor + convert chunk -------------
__global__ void k3_gen_conv(const float* __restrict__ c,
                            const float* __restrict__ W1a, const float* __restrict__ b1a,
                            const float* __restrict__ W2a, const float* __restrict__ b2a,
                            const float* __restrict__ Wb,  const float* __restrict__ bb,
                            const float* __restrict__ coeffs,
                            __half* __restrict__ g16a, __half* __restrict__ g16b,
                            float* __restrict__ biasor,
                            const float* __restrict__ W1b, const float* __restrict__ W2b,
                            __half* __restrict__ W16)
{
    int bx = blockIdx.x;
    if (bx >= 384) { convert_chunk(bx - 384 + CV1 + CV2, W1b, W2b, W16); return; }

    bool isB = (bx >= 256);
    const float* B;
    const float* bias;
    __half* g16 = nullptr;
    int ldb, kz = 0, m0, n0;
    if (isB) {
        int r = bx - 256;
        n0 = (r & 15) * 64; m0 = (r >> 4) * 64;
        B = Wb; bias = bb; ldb = OUT_DIM;
    } else {
        int z = bx >> 5, r = bx & 31;
        kz = z & 3;
        n0 = (r & 3) * 64; m0 = (r >> 2) * 64;
        B = (z < 4 ? W1a : W2a) + (long)kz * C_DIM * C_DIM;
        bias = (z < 4 ? b1a : b2a) + kz * C_DIM;
        g16 = (z < 4 ? g16a : g16b);
        ldb = C_DIM;
    }

    __shared__ float As[32][64];
    __shared__ float Bs[32][64];
    float acc[4][4] = {};
    gemm64_bk32<C_DIM>(c, C_DIM, m0, B, ldb, n0, acc, As, Bs);

    int tid = threadIdx.x;
    int tx = tid % 16, ty = tid / 16;
#pragma unroll
    for (int i = 0; i < 4; i++) {
        int m = m0 + ty * 4 + i;
        float cf = isB ? 1.0f : coeffs[m * K_EXP + kz];
#pragma unroll
        for (int j = 0; j < 4; j++) {
            int n = n0 + tx * 4 + j;
            float v = acc[i][j] + bias[n];
            if (isB) {
                biasor[m * OUT_DIM + n] = v;
            } else {
                v = cf * silu_f(v);
                g16[m * KC + kz * C_DIM + n] = __float2half(v);
            }
        }
    }
}

// -------------------- big GEMM on mma.sync (fp16) --------------------------
// 128 threads, 4 warps of 64x64 (2x2). 3-stage cp.async ring + wait_group 1,
// one __syncthreads per iter. 96 KB smem -> 2 CTAs/SM.
#define STG_SZ 32768
#define B_OFF 16384
#define NSTG 3
#define BGEMM_SMEM (NSTG * STG_SZ)   // 96 KB

__global__ void __launch_bounds__(128, 2) bgemm_half(
    const __half* __restrict__ A16a, const __half* __restrict__ A16b,
    const __half* __restrict__ W16,
    __half* __restrict__ Mbuf,
    const float* __restrict__ bB1, const float* __restrict__ bB2,
    const float* __restrict__ coeffs)
{
    extern __shared__ __align__(128) char smem[];
    const uint32_t sbase = smem_u32(smem);
    const int tid = threadIdx.x, wid = tid >> 5, lane = tid & 31;
    const int m0 = blockIdx.x * 128, n0 = blockIdx.y * 128;
    const int z = blockIdx.z;
    const int warp_m = wid & 1, warp_n = wid >> 1;   // 2 x 2

    const __half* A16 = z ? A16b : A16a;
    const __half* W = W16 + (size_t)z * W_ELEMS;
    const float* bB = z ? bB2 : bB1;
    __half* Mout = Mbuf + (size_t)z * T_TOK * D_BIG;

    float acc[4][8][4] = {};

    // cp.async geometry (128 threads):
    // A: 128 rows x 8 16B-chunks; chunk = i*128+tid -> row = i*16+(tid>>3), q = tid&7
    // B: 64 rows x 16 16B-chunks; chunk = i*128+tid -> row = i*8+(tid>>4), q = tid&15
    const int a_r = tid >> 3, a_q = tid & 7;
    const int b_r = tid >> 4, b_q = tid & 15;

    // warp ldmatrix geometry
    const int aRow = warp_m * 64 + (lane & 15);
    const uint32_t axor = ((uint32_t)(aRow & 7)) << 4;
    const uint32_t aKhalf = ((lane >> 4) & 1) * 16;
    uint32_t kOff[4];
#pragma unroll
    for (int ks = 0; ks < 4; ks++)
        kOff[ks] = ((uint32_t)(ks * 32) + aKhalf) ^ axor;
    const uint32_t aBase = (uint32_t)aRow * 128;

    const int kLoc = (lane & 7) | (((lane >> 3) & 1) << 3);
    const uint32_t bxor = ((uint32_t)(kLoc & 7)) << 4;
    const uint32_t bBase = (uint32_t)kLoc * 256;
    uint32_t nbp[4];
#pragma unroll
    for (int p = 0; p < 4; p++)
        nbp[p] = ((uint32_t)((warp_n * 64 + p * 16 + ((lane >> 4) & 1) * 8) * 2)) ^ bxor;

    auto issue = [&](int it, int buf) {
        uint32_t s = sbase + buf * STG_SZ;
        int k0 = it * 64;
#pragma unroll
        for (int i = 0; i < 8; i++) {
            int m = i * 16 + a_r;
            const __half* src = A16 + (size_t)(m0 + m) * KC + k0 + a_q * 8;
            uint32_t dst = s + (uint32_t)m * 128 +
                           (((uint32_t)(a_q * 16)) ^ (((uint32_t)(m & 7)) << 4));
            CP_ASYNC16(dst, src);
        }
#pragma unroll
        for (int i = 0; i < 8; i++) {
            int r = i * 8 + b_r;
            const __half* src = W + (size_t)(k0 + r) * D_BIG + n0 + b_q * 8;
            uint32_t dst = s + B_OFF + (uint32_t)r * 256 +
                           (((uint32_t)(b_q * 16)) ^ (((uint32_t)(r & 7)) << 4));
            CP_ASYNC16(dst, src);
        }
        CP_COMMIT();
    };
    auto mmaStage = [&](int buf) {
        uint32_t sA = sbase + buf * STG_SZ;
        uint32_t sB = sA + B_OFF;
#pragma unroll
        for (int ks = 0; ks < 4; ks++) {
            uint32_t ah[4][4], bb[4][4];
#pragma unroll
            for (int mt = 0; mt < 4; mt++)
                LDSM4(ah[mt], sA + aBase + mt * 2048 + kOff[ks]);
#pragma unroll
            for (int p = 0; p < 4; p++)
                LDSM4T(bb[p], sB + ks * 4096 + bBase + nbp[p]);
#pragma unroll
            for (int mt = 0; mt < 4; mt++)
#pragma unroll
                for (int nt = 0; nt < 8; nt++)
                    MMA_F16(acc[mt][nt], ah[mt],
                            bb[nt >> 1][(nt & 1) * 2], bb[nt >> 1][(nt & 1) * 2 + 1]);
        }
    };

    // prologue: 2 stages in flight
    issue(0, 0);
    issue(1, 1);

    int buf = 0;
    for (int it = 0; it < 16; ++it) {
        if (it < 15) CP_WAIT1(); else CP_WAIT0();
        __syncthreads();
        if (it + 2 < 16) {
            int nb = buf + 2; if (nb >= 3) nb -= 3;
            issue(it + 2, nb);
        }
        mmaStage(buf);
        if (++buf == 3) buf = 0;
    }

    // epilogue: mixed-expert bias, fp16 stores (warp covers 64 m x 64 n)
    const int mw = m0 + warp_m * 64;
    const int nw = n0 + warp_n * 64;
    const int row = lane >> 2, colq = (lane & 3) * 2;
#pragma unroll
    for (int nt = 0; nt < 8; nt++) {
        int n = nw + nt * 8 + colq;
        float bv[K_EXP][2];
#pragma unroll
        for (int e = 0; e < K_EXP; e++) {
            bv[e][0] = bB[(size_t)e * D_BIG + n];
            bv[e][1] = bB[(size_t)e * D_BIG + n + 1];
        }
#pragma unroll
        for (int mt = 0; mt < 4; mt++) {
            int m = mw + mt * 16 + row;
            float4 c0 = *(const float4*)(coeffs + m * 4);
            float4 c1 = *(const float4*)(coeffs + (m + 8) * 4);
            float b00 = c0.x * bv[0][0] + c0.y * bv[1][0] + c0.z * bv[2][0] + c0.w * bv[3][0];
            float b01 = c0.x * bv[0][1] + c0.y * bv[1][1] + c0.z * bv[2][1] + c0.w * bv[3][1];
            float b10 = c1.x * bv[0][0] + c1.y * bv[1][0] + c1.z * bv[2][0] + c1.w * bv[3][0];
            float b11 = c1.x * bv[0][1] + c1.y * bv[1][1] + c1.z * bv[2][1] + c1.w * bv[3][1];
            __half2 h0 = __floats2half2_rn(acc[mt][nt][0] + b00, acc[mt][nt][1] + b01);
            __half2 h1 = __floats2half2_rn(acc[mt][nt][2] + b10, acc[mt][nt][3] + b11);
            *(__half2*)(Mout + (size_t)m * D_BIG + n) = h0;
            *(__half2*)(Mout + (size_t)(m + 8) * D_BIG + n) = h1;
        }
    }
}

// -------------------- Monarch stage: per-(token,g) 32x32 GEMV (fp16 M) -----
template<int STAGE>
__global__ void monarch_kernel(const float* __restrict__ X,
                               const __half* __restrict__ Mbuf,
                               float* __restrict__ out,
                               const float* __restrict__ ratio,
                               const float* __restrict__ biasor)
{
    __shared__ float xs[1024];
    int t = blockIdx.x;
    int tid = threadIdx.x;   // 256
#pragma unroll
    for (int i = tid; i < 1024; i += 256) xs[i] = X[t * 1024 + i];
    __syncthreads();

    int o = tid & 31, w = tid >> 5;
    const __half* Mrow = Mbuf + (size_t)t * D_BIG;
#pragma unroll
    for (int gi = 0; gi < 4; gi++) {
        int g = w * 4 + gi;
        float acc = 0.0f;
        const __half* mp = Mrow + g * 1024 + o;
#pragma unroll
        for (int i = 0; i < 32; i++) acc += xs[g * 32 + i] * __half2float(mp[i * 32]);
        if (STAGE == 1) {
            out[t * 1024 + o * 32 + g] = acc;           // transposed for stage 2
        } else {
            int idx = t * 1024 + g * 32 + o;
            out[idx] = acc * ratio[t] + biasor[idx];
        }
    }
}

// ---------------------------------------------------------------------------
extern "C" void kernel_launch(void* const* d_in, const int* in_sizes, int n_in,
                              void* d_out, int out_size)
{
    const float* x   = (const float*)d_in[0];
    const float* Wc  = (const float*)d_in[1];
    const float* bc  = (const float*)d_in[2];
    const float* W1a = (const float*)d_in[3];
    const float* b1a = (const float*)d_in[4];
    const float* W1b = (const float*)d_in[5];
    const float* b1b = (const float*)d_in[6];
    const float* W2a = (const float*)d_in[7];
    const float* b2a = (const float*)d_in[8];
    const float* W2b = (const float*)d_in[9];
    const float* b2b = (const float*)d_in[10];
    const float* Wm1 = (const float*)d_in[11];
    const float* bm1 = (const float*)d_in[12];
    const float* Wm2 = (const float*)d_in[13];
    const float* bm2 = (const float*)d_in[14];
    const float* Wb  = (const float*)d_in[15];
    const float* bb  = (const float*)d_in[16];
    const float* Wr  = (const float*)d_in[17];
    const float* br  = (const float*)d_in[18];
    float* out = (float*)d_out;

    float *p_c, *p_co, *p_ra, *p_bi, *p_x1;
    __half *p_a, *p_b, *p_M, *p_w16;
    cudaGetSymbolAddress((void**)&p_c,   g_c);
    cudaGetSymbolAddress((void**)&p_a,   g_A16a);
    cudaGetSymbolAddress((void**)&p_b,   g_A16b);
    cudaGetSymbolAddress((void**)&p_co,  g_coeffs);
    cudaGetSymbolAddress((void**)&p_ra,  g_ratio);
    cudaGetSymbolAddress((void**)&p_bi,  g_biasor);
    cudaGetSymbolAddress((void**)&p_x1,  g_x1oT);
    cudaGetSymbolAddress((void**)&p_M,   g_M);
    cudaGetSymbolAddress((void**)&p_w16, g_W16);

    static bool attr_done = false;
    if (!attr_done) {
        cudaFuncSetAttribute(bgemm_half,
                             cudaFuncAttributeMaxDynamicSharedMemorySize,
                             BGEMM_SMEM);
        attr_done = true;
    }

    // L1: c = silu(x @ Wc + bc)  +  convert chunk 1
    k1_c_conv<<<32 + CV1, 256>>>(x, Wc, p_c, bc, W1b, W2b, p_w16);

    // L2: coeffs/ratio  +  convert chunk 2
    k2_mix_conv<<<512 + CV2, 256>>>(p_c, Wm1, bm1, Wm2, bm2, Wr, br,
                                    p_co, p_ra, W1b, W2b, p_w16);

    // L3: expert-gens (both stages) + biasor  +  convert chunk 3
    k3_gen_conv<<<384 + CV3, 256>>>(p_c, W1a, b1a, W2a, b2a, Wb, bb, p_co,
                                    p_a, p_b, p_bi, W1b, W2b, p_w16);

    // merged bgemm (z picks stage), 4 warps of 64x64, 2 CTAs/SM
    bgemm_half<<<dim3(T_TOK / 128, D_BIG / 128, 2), 128, BGEMM_SMEM>>>(
        p_a, p_b, p_w16, p_M, b1b, b2b, p_co);

    // Monarch stage 1 (writes transposed)
    monarch_kernel<1><<<T_TOK, 256>>>(x, p_M, p_x1, nullptr, nullptr);

    // Monarch stage 2 + final epilogue
    monarch_kernel<2><<<T_TOK, 256>>>(
        p_x1, p_M + (size_t)T_TOK * D_BIG, out, p_ra, p_bi);
}

// round 17
// speedup vs baseline: 1.7079x; 1.0305x over previous
#include <cuda_runtime.h>
#include <cuda_bf16.h>
#include <cuda_fp16.h>
#include <cstdint>
#include <cstddef>

// ---------------------------------------------------------------------------
// HyperMoMixLinear on GB300 (sm_103a harness, PLAIN sm_103 ptx target).
// R17: bgemm kept at R16 (64x64 warp tiles, tensor 67%, near smem-port
// co-saturation floor). Non-GEMM path (180us) attacked:
//   - monarch stage1+stage2 merged into ONE per-token kernel (smem handoff,
//     bitwise-identical math, one less launch, no x1oT round-trip)
//   - convert chunks rebalanced toward the compute-light launches.
// ---------------------------------------------------------------------------

#define T_TOK 512
#define C_DIM 256
#define IN_DIM 1024
#define OUT_DIM 1024
#define K_EXP 4
#define D_BIG 32768
#define KC 1024   // K_EXP * C_DIM  == GEMM K
#define W_ELEMS ((size_t)KC * D_BIG)

// convert work: 16384 chunks per weight, 32768 total; split across 3 launches
#define CV1 14336
#define CV2 6144
#define CV3 12288   // CV1+CV2+CV3 == 32768

// -------------------- device scratch (no runtime allocation) ---------------
__device__ float g_c[T_TOK * C_DIM];
__device__ __half g_A16a[T_TOK * KC];
__device__ __half g_A16b[T_TOK * KC];
__device__ float g_coeffs[T_TOK * K_EXP];
__device__ float g_ratio[T_TOK];
__device__ float g_biasor[T_TOK * OUT_DIM];
__device__ __half g_M[2 * (size_t)T_TOK * D_BIG];  // 2 x 32 MB (M1, M2)
__device__ __half g_W16[2 * W_ELEMS];              // 128 MB fp16 weights

__device__ __forceinline__ float silu_f(float v) {
    return v / (1.0f + __expf(-v));
}

__device__ __forceinline__ uint32_t smem_u32(const void* p) {
    uint32_t a;
    asm("{ .reg .u64 t; cvta.to.shared.u64 t, %1; cvt.u32.u64 %0, t; }"
        : "=r"(a) : "l"(p));
    return a;
}

#define CP_ASYNC16(dst, src) \
    asm volatile("cp.async.cg.shared.global [%0], [%1], 16;" \
                 :: "r"(dst), "l"(src) : "memory")
#define CP_COMMIT() asm volatile("cp.async.commit_group;" ::: "memory")
#define CP_WAIT0()  asm volatile("cp.async.wait_group 0;" ::: "memory")
#define CP_WAIT1()  asm volatile("cp.async.wait_group 1;" ::: "memory")

#define LDSM4(r, addr) \
    asm volatile("ldmatrix.sync.aligned.m8n8.x4.shared.b16 {%0,%1,%2,%3}, [%4];" \
        : "=r"((r)[0]), "=r"((r)[1]), "=r"((r)[2]), "=r"((r)[3]) : "r"(addr))
#define LDSM4T(r, addr) \
    asm volatile("ldmatrix.sync.aligned.m8n8.x4.trans.shared.b16 {%0,%1,%2,%3}, [%4];" \
        : "=r"((r)[0]), "=r"((r)[1]), "=r"((r)[2]), "=r"((r)[3]) : "r"(addr))

#define MMA_F16(d, a, b0v, b1v) \
    asm volatile("mma.sync.aligned.m16n8k16.row.col.f32.f16.f16.f32 " \
        "{%0,%1,%2,%3}, {%4,%5,%6,%7}, {%8,%9}, {%0,%1,%2,%3};" \
        : "+f"((d)[0]), "+f"((d)[1]), "+f"((d)[2]), "+f"((d)[3]) \
        : "r"((a)[0]), "r"((a)[1]), "r"((a)[2]), "r"((a)[3]), \
          "r"(b0v), "r"(b1v))

// -------------------- convert chunk (one block's share) --------------------
__device__ __forceinline__ void convert_chunk(int cb,
                                              const float* __restrict__ W1b,
                                              const float* __restrict__ W2b,
                                              __half* __restrict__ W16)
{
    const float* W = (cb >= 16384) ? W2b : W1b;
    __half* dst = W16 + ((cb >= 16384) ? W_ELEMS : 0);
    int b = cb & 16383;
    size_t base = ((size_t)b * 256 + threadIdx.x) * 8;
    float4 v0 = *(const float4*)(W + base);
    float4 v1 = *(const float4*)(W + base + 4);
    __half2 h0 = __floats2half2_rn(v0.x, v0.y);
    __half2 h1 = __floats2half2_rn(v0.z, v0.w);
    __half2 h2 = __floats2half2_rn(v1.x, v1.y);
    __half2 h3 = __floats2half2_rn(v1.z, v1.w);
    uint4 o;
    o.x = *(uint32_t*)&h0; o.y = *(uint32_t*)&h1;
    o.z = *(uint32_t*)&h2; o.w = *(uint32_t*)&h3;
    *(uint4*)(dst + base) = o;
}

// -------------------- shared BK=32 64x64 fp32 GEMM body --------------------
template<int KD>
__device__ __forceinline__ void gemm64_bk32(
    const float* __restrict__ A, int lda, int m0,
    const float* __restrict__ B, int ldb, int n0,
    float (&acc)[4][4], float (*As)[64], float (*Bs)[64])
{
    int tid = threadIdx.x;
    int tx = tid % 16, ty = tid / 16;
    int arow = tid >> 2, aq = tid & 3;
    int brow = tid >> 3, bq = tid & 7;

    for (int k0 = 0; k0 < KD; k0 += 32) {
#pragma unroll
        for (int h = 0; h < 2; h++) {
            int qc = aq + h * 4;
            float4 av = *(const float4*)&A[(m0 + arow) * lda + k0 + qc * 4];
            As[qc * 4 + 0][arow] = av.x;
            As[qc * 4 + 1][arow] = av.y;
            As[qc * 4 + 2][arow] = av.z;
            As[qc * 4 + 3][arow] = av.w;
        }
#pragma unroll
        for (int h = 0; h < 2; h++) {
            int qc = bq + h * 8;
            *(float4*)&Bs[brow][qc * 4] =
                *(const float4*)&B[(k0 + brow) * ldb + n0 + qc * 4];
        }
        __syncthreads();
#pragma unroll
        for (int k = 0; k < 32; k++) {
            float a[4], b[4];
#pragma unroll
            for (int i = 0; i < 4; i++) a[i] = As[k][ty * 4 + i];
#pragma unroll
            for (int j = 0; j < 4; j++) b[j] = Bs[k][tx * 4 + j];
#pragma unroll
            for (int i = 0; i < 4; i++)
#pragma unroll
                for (int j = 0; j < 4; j++) acc[i][j] += a[i] * b[j];
        }
        __syncthreads();
    }
}

// -------------------- L1: compressor GEMM + convert chunk ------------------
__global__ void k1_c_conv(const float* __restrict__ x, const float* __restrict__ Wc,
                          float* __restrict__ c, const float* __restrict__ bc,
                          const float* __restrict__ W1b, const float* __restrict__ W2b,
                          __half* __restrict__ W16)
{
    int bx = blockIdx.x;
    if (bx >= 32) { convert_chunk(bx - 32, W1b, W2b, W16); return; }

    __shared__ float As[32][64];
    __shared__ float Bs[32][64];
    int m0 = (bx >> 2) * 64;
    int n0 = (bx & 3) * 64;
    float acc[4][4] = {};
    gemm64_bk32<IN_DIM>(x, IN_DIM, m0, Wc, C_DIM, n0, acc, As, Bs);

    int tid = threadIdx.x;
    int tx = tid % 16, ty = tid / 16;
#pragma unroll
    for (int i = 0; i < 4; i++) {
        int m = m0 + ty * 4 + i;
#pragma unroll
        for (int j = 0; j < 4; j++) {
            int n = n0 + tx * 4 + j;
            c[m * C_DIM + n] = silu_f(acc[i][j] + bc[n]);
        }
    }
}

// -------------------- L2: mixer + convert chunk ----------------------------
__global__ void k2_mix_conv(const float* __restrict__ c,
                            const float* __restrict__ Wm1, const float* __restrict__ bm1,
                            const float* __restrict__ Wm2, const float* __restrict__ bm2,
                            const float* __restrict__ Wr,  const float* __restrict__ br,
                            float* __restrict__ coeffs, float* __restrict__ ratio,
                            const float* __restrict__ W1b, const float* __restrict__ W2b,
                            __half* __restrict__ W16)
{
    int bx = blockIdx.x;
    if (bx >= 512) { convert_chunk(bx - 512 + CV1, W1b, W2b, W16); return; }

    __shared__ float cs[C_DIM];
    __shared__ float ms[C_DIM];
    __shared__ float red[C_DIM];
    __shared__ float lg[K_EXP];
    int t = bx, tid = threadIdx.x;

    cs[tid] = c[t * C_DIM + tid];
    __syncthreads();

    float acc = bm1[tid];
#pragma unroll 8
    for (int i = 0; i < C_DIM; i++) acc += cs[i] * Wm1[i * C_DIM + tid];
    ms[tid] = silu_f(acc);
    red[tid] = cs[tid] * Wr[tid];
    __syncthreads();

    if (tid < K_EXP) {
        float l = bm2[tid];
#pragma unroll 8
        for (int i = 0; i < C_DIM; i++) l += ms[i] * Wm2[i * K_EXP + tid];
        lg[tid] = l;
    }
    for (int s = 128; s > 0; s >>= 1) {
        __syncthreads();
        if (tid < s) red[tid] += red[tid + s];
    }
    __syncthreads();

    if (tid == 0) {
        ratio[t] = red[0] + br[0];
        float mx = fmaxf(fmaxf(lg[0], lg[1]), fmaxf(lg[2], lg[3]));
        float e0 = __expf(lg[0] - mx), e1 = __expf(lg[1] - mx);
        float e2 = __expf(lg[2] - mx), e3 = __expf(lg[3] - mx);
        float inv = 1.0f / (e0 + e1 + e2 + e3);
        coeffs[t * 4 + 0] = e0 * inv;
        coeffs[t * 4 + 1] = e1 * inv;
        coeffs[t * 4 + 2] = e2 * inv;
        coeffs[t * 4 + 3] = e3 * inv;
    }
}

// -------------------- L3: expert-gens + biasor + convert chunk -------------
__global__ void k3_gen_conv(const float* __restrict__ c,
                            const float* __restrict__ W1a, const float* __restrict__ b1a,
                            const float* __restrict__ W2a, const float* __restrict__ b2a,
                            const float* __restrict__ Wb,  const float* __restrict__ bb,
                            const float* __restrict__ coeffs,
                            __half* __restrict__ g16a, __half* __restrict__ g16b,
                            float* __restrict__ biasor,
                            const float* __restrict__ W1b, const float* __restrict__ W2b,
                            __half* __restrict__ W16)
{
    int bx = blockIdx.x;
    if (bx >= 384) { convert_chunk(bx - 384 + CV1 + CV2, W1b, W2b, W16); return; }

    bool isB = (bx >= 256);
    const float* B;
    const float* bias;
    __half* g16 = nullptr;
    int ldb, kz = 0, m0, n0;
    if (isB) {
        int r = bx - 256;
        n0 = (r & 15) * 64; m0 = (r >> 4) * 64;
        B = Wb; bias = bb; ldb = OUT_DIM;
    } else {
        int z = bx >> 5, r = bx & 31;
        kz = z & 3;
        n0 = (r & 3) * 64; m0 = (r >> 2) * 64;
        B = (z < 4 ? W1a : W2a) + (long)kz * C_DIM * C_DIM;
        bias = (z < 4 ? b1a : b2a) + kz * C_DIM;
        g16 = (z < 4 ? g16a : g16b);
        ldb = C_DIM;
    }

    __shared__ float As[32][64];
    __shared__ float Bs[32][64];
    float acc[4][4] = {};
    gemm64_bk32<C_DIM>(c, C_DIM, m0, B, ldb, n0, acc, As, Bs);

    int tid = threadIdx.x;
    int tx = tid % 16, ty = tid / 16;
#pragma unroll
    for (int i = 0; i < 4; i++) {
        int m = m0 + ty * 4 + i;
        float cf = isB ? 1.0f : coeffs[m * K_EXP + kz];
#pragma unroll
        for (int j = 0; j < 4; j++) {
            int n = n0 + tx * 4 + j;
            float v = acc[i][j] + bias[n];
            if (isB) {
                biasor[m * OUT_DIM + n] = v;
            } else {
                v = cf * silu_f(v);
                g16[m * KC + kz * C_DIM + n] = __float2half(v);
            }
        }
    }
}

// -------------------- big GEMM on mma.sync (fp16) --------------------------
// 128 threads, 4 warps of 64x64 (2x2). 3-stage cp.async ring + wait_group 1,
// one __syncthreads per iter. 96 KB smem -> 2 CTAs/SM. (R16 configuration.)
#define STG_SZ 32768
#define B_OFF 16384
#define NSTG 3
#define BGEMM_SMEM (NSTG * STG_SZ)   // 96 KB

__global__ void __launch_bounds__(128, 2) bgemm_half(
    const __half* __restrict__ A16a, const __half* __restrict__ A16b,
    const __half* __restrict__ W16,
    __half* __restrict__ Mbuf,
    const float* __restrict__ bB1, const float* __restrict__ bB2,
    const float* __restrict__ coeffs)
{
    extern __shared__ __align__(128) char smem[];
    const uint32_t sbase = smem_u32(smem);
    const int tid = threadIdx.x, wid = tid >> 5, lane = tid & 31;
    const int m0 = blockIdx.x * 128, n0 = blockIdx.y * 128;
    const int z = blockIdx.z;
    const int warp_m = wid & 1, warp_n = wid >> 1;   // 2 x 2

    const __half* A16 = z ? A16b : A16a;
    const __half* W = W16 + (size_t)z * W_ELEMS;
    const float* bB = z ? bB2 : bB1;
    __half* Mout = Mbuf + (size_t)z * T_TOK * D_BIG;

    float acc[4][8][4] = {};

    const int a_r = tid >> 3, a_q = tid & 7;
    const int b_r = tid >> 4, b_q = tid & 15;

    const int aRow = warp_m * 64 + (lane & 15);
    const uint32_t axor = ((uint32_t)(aRow & 7)) << 4;
    const uint32_t aKhalf = ((lane >> 4) & 1) * 16;
    uint32_t kOff[4];
#pragma unroll
    for (int ks = 0; ks < 4; ks++)
        kOff[ks] = ((uint32_t)(ks * 32) + aKhalf) ^ axor;
    const uint32_t aBase = (uint32_t)aRow * 128;

    const int kLoc = (lane & 7) | (((lane >> 3) & 1) << 3);
    const uint32_t bxor = ((uint32_t)(kLoc & 7)) << 4;
    const uint32_t bBase = (uint32_t)kLoc * 256;
    uint32_t nbp[4];
#pragma unroll
    for (int p = 0; p < 4; p++)
        nbp[p] = ((uint32_t)((warp_n * 64 + p * 16 + ((lane >> 4) & 1) * 8) * 2)) ^ bxor;

    auto issue = [&](int it, int buf) {
        uint32_t s = sbase + buf * STG_SZ;
        int k0 = it * 64;
#pragma unroll
        for (int i = 0; i < 8; i++) {
            int m = i * 16 + a_r;
            const __half* src = A16 + (size_t)(m0 + m) * KC + k0 + a_q * 8;
            uint32_t dst = s + (uint32_t)m * 128 +
                           (((uint32_t)(a_q * 16)) ^ (((uint32_t)(m & 7)) << 4));
            CP_ASYNC16(dst, src);
        }
#pragma unroll
        for (int i = 0; i < 8; i++) {
            int r = i * 8 + b_r;
            const __half* src = W + (size_t)(k0 + r) * D_BIG + n0 + b_q * 8;
            uint32_t dst = s + B_OFF + (uint32_t)r * 256 +
                           (((uint32_t)(b_q * 16)) ^ (((uint32_t)(r & 7)) << 4));
            CP_ASYNC16(dst, src);
        }
        CP_COMMIT();
    };
    auto mmaStage = [&](int buf) {
        uint32_t sA = sbase + buf * STG_SZ;
        uint32_t sB = sA + B_OFF;
#pragma unroll
        for (int ks = 0; ks < 4; ks++) {
            uint32_t ah[4][4], bb[4][4];
#pragma unroll
            for (int mt = 0; mt < 4; mt++)
                LDSM4(ah[mt], sA + aBase + mt * 2048 + kOff[ks]);
#pragma unroll
            for (int p = 0; p < 4; p++)
                LDSM4T(bb[p], sB + ks * 4096 + bBase + nbp[p]);
#pragma unroll
            for (int mt = 0; mt < 4; mt++)
#pragma unroll
                for (int nt = 0; nt < 8; nt++)
                    MMA_F16(acc[mt][nt], ah[mt],
                            bb[nt >> 1][(nt & 1) * 2], bb[nt >> 1][(nt & 1) * 2 + 1]);
        }
    };

    issue(0, 0);
    issue(1, 1);

    int buf = 0;
    for (int it = 0; it < 16; ++it) {
        if (it < 15) CP_WAIT1(); else CP_WAIT0();
        __syncthreads();
        if (it + 2 < 16) {
            int nb = buf + 2; if (nb >= 3) nb -= 3;
            issue(it + 2, nb);
        }
        mmaStage(buf);
        if (++buf == 3) buf = 0;
    }

    const int mw = m0 + warp_m * 64;
    const int nw = n0 + warp_n * 64;
    const int row = lane >> 2, colq = (lane & 3) * 2;
#pragma unroll
    for (int nt = 0; nt < 8; nt++) {
        int n = nw + nt * 8 + colq;
        float bv[K_EXP][2];
#pragma unroll
        for (int e = 0; e < K_EXP; e++) {
            bv[e][0] = bB[(size_t)e * D_BIG + n];
            bv[e][1] = bB[(size_t)e * D_BIG + n + 1];
        }
#pragma unroll
        for (int mt = 0; mt < 4; mt++) {
            int m = mw + mt * 16 + row;
            float4 c0 = *(const float4*)(coeffs + m * 4);
            float4 c1 = *(const float4*)(coeffs + (m + 8) * 4);
            float b00 = c0.x * bv[0][0] + c0.y * bv[1][0] + c0.z * bv[2][0] + c0.w * bv[3][0];
            float b01 = c0.x * bv[0][1] + c0.y * bv[1][1] + c0.z * bv[2][1] + c0.w * bv[3][1];
            float b10 = c1.x * bv[0][0] + c1.y * bv[1][0] + c1.z * bv[2][0] + c1.w * bv[3][0];
            float b11 = c1.x * bv[0][1] + c1.y * bv[1][1] + c1.z * bv[2][1] + c1.w * bv[3][1];
            __half2 h0 = __floats2half2_rn(acc[mt][nt][0] + b00, acc[mt][nt][1] + b01);
            __half2 h1 = __floats2half2_rn(acc[mt][nt][2] + b10, acc[mt][nt][3] + b11);
            *(__half2*)(Mout + (size_t)m * D_BIG + n) = h0;
            *(__half2*)(Mout + (size_t)(m + 8) * D_BIG + n) = h1;
        }
    }
}

// -------------------- fused Monarch: stage1 -> smem -> stage2 --------------
// One block per token. Stage1 writes y[o*32+g] (the old x1oT layout) into
// smem; stage2 reads it as its input. Bitwise-identical to the two-kernel
// version (same per-element arithmetic order).
__global__ void monarch_fused(const float* __restrict__ X,
                              const __half* __restrict__ M1,
                              const __half* __restrict__ M2,
                              float* __restrict__ out,
                              const float* __restrict__ ratio,
                              const float* __restrict__ biasor)
{
    __shared__ float xs[1024];
    __shared__ float y1[1024];
    int t = blockIdx.x;
    int tid = threadIdx.x;   // 256
#pragma unroll
    for (int i = tid; i < 1024; i += 256) xs[i] = X[t * 1024 + i];
    __syncthreads();

    int o = tid & 31, w = tid >> 5;

    // stage 1: y1[o*32+g] = sum_i xs[g*32+i] * M1[t, g*1024 + i*32 + o]
    {
        const float* xv = xs;
        const __half* Mrow = M1 + (size_t)t * D_BIG;
#pragma unroll
        for (int gi = 0; gi < 4; gi++) {
            int g = w * 4 + gi;
            float acc = 0.0f;
            const __half* mp = Mrow + g * 1024 + o;
#pragma unroll
            for (int i = 0; i < 32; i++) acc += xv[g * 32 + i] * __half2float(mp[i * 32]);
            y1[o * 32 + g] = acc;
        }
    }
    __syncthreads();

    // stage 2: out[t, g*32+o] = (sum_i y1[g*32+i]*M2[...]) * ratio + biasor
    {
        const __half* Mrow = M2 + (size_t)t * D_BIG;
        float rt = ratio[t];
#pragma unroll
        for (int gi = 0; gi < 4; gi++) {
            int g = w * 4 + gi;
            float acc = 0.0f;
            const __half* mp = Mrow + g * 1024 + o;
#pragma unroll
            for (int i = 0; i < 32; i++) acc += y1[g * 32 + i] * __half2float(mp[i * 32]);
            int idx = t * 1024 + g * 32 + o;
            out[idx] = acc * rt + biasor[idx];
        }
    }
}

// ---------------------------------------------------------------------------
extern "C" void kernel_launch(void* const* d_in, const int* in_sizes, int n_in,
                              void* d_out, int out_size)
{
    const float* x   = (const float*)d_in[0];
    const float* Wc  = (const float*)d_in[1];
    const float* bc  = (const float*)d_in[2];
    const float* W1a = (const float*)d_in[3];
    const float* b1a = (const float*)d_in[4];
    const float* W1b = (const float*)d_in[5];
    const float* b1b = (const float*)d_in[6];
    const float* W2a = (const float*)d_in[7];
    const float* b2a = (const float*)d_in[8];
    const float* W2b = (const float*)d_in[9];
    const float* b2b = (const float*)d_in[10];
    const float* Wm1 = (const float*)d_in[11];
    const float* bm1 = (const float*)d_in[12];
    const float* Wm2 = (const float*)d_in[13];
    const float* bm2 = (const float*)d_in[14];
    const float* Wb  = (const float*)d_in[15];
    const float* bb  = (const float*)d_in[16];
    const float* Wr  = (const float*)d_in[17];
    const float* br  = (const float*)d_in[18];
    float* out = (float*)d_out;

    float *p_c, *p_co, *p_ra, *p_bi;
    __half *p_a, *p_b, *p_M, *p_w16;
    cudaGetSymbolAddress((void**)&p_c,   g_c);
    cudaGetSymbolAddress((void**)&p_a,   g_A16a);
    cudaGetSymbolAddress((void**)&p_b,   g_A16b);
    cudaGetSymbolAddress((void**)&p_co,  g_coeffs);
    cudaGetSymbolAddress((void**)&p_ra,  g_ratio);
    cudaGetSymbolAddress((void**)&p_bi,  g_biasor);
    cudaGetSymbolAddress((void**)&p_M,   g_M);
    cudaGetSymbolAddress((void**)&p_w16, g_W16);

    static bool attr_done = false;
    if (!attr_done) {
        cudaFuncSetAttribute(bgemm_half,
                             cudaFuncAttributeMaxDynamicSharedMemorySize,
                             BGEMM_SMEM);
        attr_done = true;
    }

    // L1: c = silu(x @ Wc + bc)  +  convert chunk 1
    k1_c_conv<<<32 + CV1, 256>>>(x, Wc, p_c, bc, W1b, W2b, p_w16);

    // L2: coeffs/ratio  +  convert chunk 2
    k2_mix_conv<<<512 + CV2, 256>>>(p_c, Wm1, bm1, Wm2, bm2, Wr, br,
                                    p_co, p_ra, W1b, W2b, p_w16);

    // L3: expert-gens (both stages) + biasor  +  convert chunk 3
    k3_gen_conv<<<384 + CV3, 256>>>(p_c, W1a, b1a, W2a, b2a, Wb, bb, p_co,
                                    p_a, p_b, p_bi, W1b, W2b, p_w16);

    // merged bgemm (z picks stage), 4 warps of 64x64, 2 CTAs/SM
    bgemm_half<<<dim3(T_TOK / 128, D_BIG / 128, 2), 128, BGEMM_SMEM>>>(
        p_a, p_b, p_w16, p_M, b1b, b2b, p_co);

    // fused Monarch stage1+stage2 (one launch, smem handoff)
    monarch_fused<<<T_TOK, 256>>>(x, p_M, p_M + (size_t)T_TOK * D_BIG,
                                  out, p_ra, p_bi);
}